// round 6
// baseline (speedup 1.0000x reference)
#include <cuda_runtime.h>
#include <cuda_bf16.h>

#define NN 10000
#define NE 640000
#define DD 128
#define TILE_E 64
#define AS_STRIDE 388   // 384 + 4 pad
#define WS_STRIDE 132
#define SMEM_BYTES ((TILE_E*AS_STRIDE + 32*WS_STRIDE) * 4)

__device__ float g_sums[NN * DD];
__device__ float g_cnt[NN];
__device__ int   g_idx64;

// ---------------------------------------------------------------------------
// Kernel 0: zero scratch + detect edge_index dtype (int32 vs int64).
// JAX without x64 silently returns int32 for jnp.int64 randint; detect by
// checking odd 32-bit words (all zero => little-endian int64, small values).
// ---------------------------------------------------------------------------
__global__ void zero_kernel(const unsigned* ei_words) {
    int i = blockIdx.x * 256 + threadIdx.x;
    if (i < NN * DD) g_sums[i] = 0.0f;
    if (i < NN)      g_cnt[i]  = 0.0f;
    if (i == 0) {
        int all0 = 1;
        #pragma unroll
        for (int k = 1; k < 64; k += 2) all0 &= (ei_words[k] == 0u);
        g_idx64 = all0;
    }
}

__device__ __forceinline__ void red_add_v4(float* addr, float a, float b, float c, float d) {
    asm volatile("red.global.add.v4.f32 [%0], {%1, %2, %3, %4};"
                 :: "l"(addr), "f"(a), "f"(b), "f"(c), "f"(d) : "memory");
}

// ---------------------------------------------------------------------------
// Edge kernel: fused 3-layer MLP over 64-edge tiles + atomic scatter.
// Block 256 = 16x16; each thread owns 4 rows x 8 cols
// (cols tx*4..tx*4+3 and 64+tx*4..64+tx*4+3, LDS.128-friendly).
// ---------------------------------------------------------------------------
__device__ __forceinline__ float f4elem(const float4& v, int k) {
    return (k == 0) ? v.x : (k == 1) ? v.y : (k == 2) ? v.z : v.w;
}

template<int KLEN, bool RELU>
__device__ __forceinline__ void tile_gemm(
    const float* __restrict__ As, float* __restrict__ Ws,
    const float* __restrict__ W, const float* __restrict__ bias,
    int inOff, float acc[4][8], int tx, int ty, int tid)
{
    #pragma unroll
    for (int i = 0; i < 4; i++)
        #pragma unroll
        for (int j = 0; j < 8; j++) acc[i][j] = 0.0f;

    const int r0 = ty * 4;
    for (int k0 = 0; k0 < KLEN; k0 += 32) {
        __syncthreads();
        // stage 32x128 weight chunk
        #pragma unroll
        for (int i = tid; i < 32 * 128; i += 256) {
            int kk = i >> 7, c = i & 127;
            Ws[kk * WS_STRIDE + c] = W[(k0 + kk) * DD + c];
        }
        __syncthreads();
        #pragma unroll
        for (int kq = 0; kq < 8; kq++) {
            float4 a4[4];
            #pragma unroll
            for (int i = 0; i < 4; i++)
                a4[i] = *(const float4*)&As[(r0 + i) * AS_STRIDE + inOff + k0 + kq * 4];
            #pragma unroll
            for (int kk = 0; kk < 4; kk++) {
                float4 bA = *(const float4*)&Ws[(kq * 4 + kk) * WS_STRIDE + tx * 4];
                float4 bB = *(const float4*)&Ws[(kq * 4 + kk) * WS_STRIDE + 64 + tx * 4];
                #pragma unroll
                for (int i = 0; i < 4; i++) {
                    float a = f4elem(a4[i], kk);
                    acc[i][0] += a * bA.x; acc[i][1] += a * bA.y;
                    acc[i][2] += a * bA.z; acc[i][3] += a * bA.w;
                    acc[i][4] += a * bB.x; acc[i][5] += a * bB.y;
                    acc[i][6] += a * bB.z; acc[i][7] += a * bB.w;
                }
            }
        }
    }
    // bias (+ReLU)
    float4 c1 = *(const float4*)&bias[tx * 4];
    float4 c2 = *(const float4*)&bias[64 + tx * 4];
    #pragma unroll
    for (int i = 0; i < 4; i++) {
        acc[i][0] += c1.x; acc[i][1] += c1.y; acc[i][2] += c1.z; acc[i][3] += c1.w;
        acc[i][4] += c2.x; acc[i][5] += c2.y; acc[i][6] += c2.z; acc[i][7] += c2.w;
        if (RELU) {
            #pragma unroll
            for (int j = 0; j < 8; j++) acc[i][j] = fmaxf(acc[i][j], 0.0f);
        }
    }
}

__global__ void __launch_bounds__(256, 1)
edge_kernel(const float* __restrict__ x, const void* __restrict__ ei,
            const float* __restrict__ ea,
            const float* __restrict__ W1, const float* __restrict__ b1,
            const float* __restrict__ W2, const float* __restrict__ b2,
            const float* __restrict__ W3, const float* __restrict__ b3)
{
    extern __shared__ float sm[];
    float* As = sm;                         // 64 x AS_STRIDE
    float* Ws = sm + TILE_E * AS_STRIDE;    // 32 x WS_STRIDE
    __shared__ int sDst[TILE_E], sSrc[TILE_E];

    const int tid = threadIdx.x;
    const int tx = tid & 15, ty = tid >> 4;
    const int e0 = blockIdx.x * TILE_E;

    if (tid < TILE_E) {
        int e = e0 + tid;
        long long s, d;
        if (g_idx64) {
            const long long* p = (const long long*)ei;
            s = p[e]; d = p[NE + e];
        } else {
            const int* p = (const int*)ei;
            s = p[e]; d = p[NE + e];
        }
        sSrc[tid] = (int)s; sDst[tid] = (int)d;
    }
    __syncthreads();

    // gather A tile: [x[dst] | edge_attr | x[src]] as float4
    for (int i = tid; i < TILE_E * 32; i += 256) {
        int e = i >> 5;
        int k4 = (i & 31) * 4;
        float* row = &As[e * AS_STRIDE];
        *(float4*)&row[k4]       = *(const float4*)&x[(size_t)sDst[e] * DD + k4];
        *(float4*)&row[128 + k4] = *(const float4*)&ea[(size_t)(e0 + e) * DD + k4];
        *(float4*)&row[256 + k4] = *(const float4*)&x[(size_t)sSrc[e] * DD + k4];
    }
    __syncthreads();

    float acc[4][8];
    const int r0 = ty * 4;

    // Layer 1: K=384, ReLU -> write m1 to As[:,0:128]
    tile_gemm<384, true>(As, Ws, W1, b1, 0, acc, tx, ty, tid);
    __syncthreads();
    #pragma unroll
    for (int i = 0; i < 4; i++) {
        float* row = &As[(r0 + i) * AS_STRIDE];
        *(float4*)&row[tx * 4]      = make_float4(acc[i][0], acc[i][1], acc[i][2], acc[i][3]);
        *(float4*)&row[64 + tx * 4] = make_float4(acc[i][4], acc[i][5], acc[i][6], acc[i][7]);
    }
    __syncthreads();

    // Layer 2: K=128, ReLU -> write m2 to As[:,128:256]
    tile_gemm<128, true>(As, Ws, W2, b2, 0, acc, tx, ty, tid);
    __syncthreads();
    #pragma unroll
    for (int i = 0; i < 4; i++) {
        float* row = &As[(r0 + i) * AS_STRIDE];
        *(float4*)&row[128 + tx * 4]       = make_float4(acc[i][0], acc[i][1], acc[i][2], acc[i][3]);
        *(float4*)&row[128 + 64 + tx * 4]  = make_float4(acc[i][4], acc[i][5], acc[i][6], acc[i][7]);
    }
    __syncthreads();

    // Layer 3: K=128, no ReLU -> scatter-add (v4 reductions, no return path)
    tile_gemm<128, false>(As, Ws, W3, b3, 128, acc, tx, ty, tid);

    #pragma unroll
    for (int i = 0; i < 4; i++) {
        int d = sDst[r0 + i];
        float* base = &g_sums[(size_t)d * DD];
        red_add_v4(&base[tx * 4],      acc[i][0], acc[i][1], acc[i][2], acc[i][3]);
        red_add_v4(&base[64 + tx * 4], acc[i][4], acc[i][5], acc[i][6], acc[i][7]);
        if (tx == 0) atomicAdd(&g_cnt[d], 1.0f);
    }
}

// ---------------------------------------------------------------------------
// Node kernel: dh = sums/cnt; h = LN(x+dh); ff; out = LN(h+ff). 1 node/block.
// ---------------------------------------------------------------------------
__device__ __forceinline__ float bsum(float v, float* red) {
    #pragma unroll
    for (int o = 16; o > 0; o >>= 1) v += __shfl_xor_sync(0xFFFFFFFFu, v, o);
    int w = threadIdx.x >> 5;
    if ((threadIdx.x & 31) == 0) red[w] = v;
    __syncthreads();
    float r = red[0] + red[1] + red[2] + red[3];
    __syncthreads();
    return r;
}

__global__ void __launch_bounds__(128)
node_kernel(const float* __restrict__ x,
            const float* __restrict__ F1, const float* __restrict__ bf1,
            const float* __restrict__ F2, const float* __restrict__ bf2,
            const float* __restrict__ g0, const float* __restrict__ be0,
            const float* __restrict__ g1, const float* __restrict__ be1,
            float* __restrict__ out)
{
    const int n = blockIdx.x;
    const int t = threadIdx.x;
    __shared__ float Hs[DD];
    __shared__ float Hid[2 * DD];
    __shared__ float red[4];

    float cnt = fmaxf(g_cnt[n], 1.0f);
    float z = x[(size_t)n * DD + t] + g_sums[(size_t)n * DD + t] / cnt;

    float mu  = bsum(z, red) * (1.0f / DD);
    float var = bsum(z * z, red) * (1.0f / DD) - mu * mu;
    float h = (z - mu) * rsqrtf(var + 1e-6f) * g0[t] + be0[t];

    Hs[t] = h;
    __syncthreads();

    float s0 = bf1[t], s1 = bf1[t + 128];
    #pragma unroll 4
    for (int k = 0; k < 128; k++) {
        float hk = Hs[k];
        s0 += hk * F1[k * 256 + t];
        s1 += hk * F1[k * 256 + t + 128];
    }
    Hid[t]       = fmaxf(s0, 0.0f);
    Hid[t + 128] = fmaxf(s1, 0.0f);
    __syncthreads();

    float o = bf2[t];
    #pragma unroll 4
    for (int k = 0; k < 256; k++) o += Hid[k] * F2[k * DD + t];

    float y = h + o;
    float mu2  = bsum(y, red) * (1.0f / DD);
    float var2 = bsum(y * y, red) * (1.0f / DD) - mu2 * mu2;
    out[(size_t)n * DD + t] = (y - mu2) * rsqrtf(var2 + 1e-6f) * g1[t] + be1[t];
}

// ---------------------------------------------------------------------------
extern "C" void kernel_launch(void* const* d_in, const int* in_sizes, int n_in,
                              void* d_out, int out_size) {
    const float* x   = (const float*)d_in[0];
    const void*  ei  = d_in[1];
    const float* ea  = (const float*)d_in[2];
    const float* W1  = (const float*)d_in[3];
    const float* b1  = (const float*)d_in[4];
    const float* W2  = (const float*)d_in[5];
    const float* b2  = (const float*)d_in[6];
    const float* W3  = (const float*)d_in[7];
    const float* b3  = (const float*)d_in[8];
    const float* F1  = (const float*)d_in[9];
    const float* bf1 = (const float*)d_in[10];
    const float* F2  = (const float*)d_in[11];
    const float* bf2 = (const float*)d_in[12];
    const float* g0  = (const float*)d_in[13];
    const float* be0 = (const float*)d_in[14];
    const float* g1  = (const float*)d_in[15];
    const float* be1 = (const float*)d_in[16];
    float* out = (float*)d_out;

    static int smem_set = 0;
    if (!smem_set) {
        cudaFuncSetAttribute(edge_kernel, cudaFuncAttributeMaxDynamicSharedMemorySize, SMEM_BYTES);
        smem_set = 1;
    }

    zero_kernel<<<(NN * DD + 255) / 256, 256>>>((const unsigned*)ei);
    edge_kernel<<<NE / TILE_E, 256, SMEM_BYTES>>>(x, ei, ea, W1, b1, W2, b2, W3, b3);
    node_kernel<<<NN, 128>>>(x, F1, bf1, F2, bf2, g0, be0, g1, be1, out);
}

// round 8
// speedup vs baseline: 1.8757x; 1.8757x over previous
#include <cuda_runtime.h>
#include <cuda_bf16.h>
#include <cstdint>

#define NN 10000
#define NE 640000
#define DD 128
#define TE 128                 // edges per CTA
#define NTILES (NE / TE)
#define AST 132                // sA row stride (floats): conflict-free A frags
#define WST 136                // sW row stride (floats): conflict-free B frags
#define EDGE_SMEM ((128 * AST + 64 * WST) * 4)   // 102,400 B dynamic

__device__ float g_sums[NN * DD];
__device__ float g_cnt[NN];
__device__ int   g_idx64;
__device__ float g_Wpack[640 * WST];   // rows: W1(384) | W2(128) | W3(128), tf32, [k][n] stride WST

// ---------------- helpers ----------------
__device__ __forceinline__ uint32_t f2tf(float f) {
    uint32_t r;
    asm("cvt.rna.tf32.f32 %0, %1;" : "=r"(r) : "f"(f));
    return r;
}
__device__ __forceinline__ void mma8(float* d, const uint32_t* a, uint32_t b0, uint32_t b1) {
    asm volatile("mma.sync.aligned.m16n8k8.row.col.f32.tf32.tf32.f32 "
                 "{%0,%1,%2,%3}, {%4,%5,%6,%7}, {%8,%9}, {%0,%1,%2,%3};"
                 : "+f"(d[0]), "+f"(d[1]), "+f"(d[2]), "+f"(d[3])
                 : "r"(a[0]), "r"(a[1]), "r"(a[2]), "r"(a[3]), "r"(b0), "r"(b1));
}
__device__ __forceinline__ void red2(float* addr, float a, float b) {
    asm volatile("red.global.add.v2.f32 [%0], {%1, %2};" :: "l"(addr), "f"(a), "f"(b) : "memory");
}
__device__ __forceinline__ void red1(float* addr, float a) {
    asm volatile("red.global.add.f32 [%0], %1;" :: "l"(addr), "f"(a) : "memory");
}

// ---------------------------------------------------------------------------
// Prep: zero scratch, sniff edge_index dtype, pack W1|W2|W3 as tf32 [k][n].
// ---------------------------------------------------------------------------
__global__ void prep_kernel(const unsigned* ei_words,
                            const float* __restrict__ W1,
                            const float* __restrict__ W2,
                            const float* __restrict__ W3) {
    int i = blockIdx.x * 256 + threadIdx.x;
    if (i < NN * DD) g_sums[i] = 0.0f;
    if (i < NN)      g_cnt[i]  = 0.0f;
    if (i == 0) {
        int all0 = 1;
        #pragma unroll
        for (int k = 1; k < 64; k += 2) all0 &= (ei_words[k] == 0u);
        g_idx64 = all0;
    }
    if (i < 640 * WST) {
        int r = i / WST, n = i % WST;
        float v = 0.0f;
        if (n < 128) {
            if (r < 384)      v = W1[r * DD + n];
            else if (r < 512) v = W2[(r - 384) * DD + n];
            else              v = W3[(r - 512) * DD + n];
        }
        uint32_t t = f2tf(v);
        g_Wpack[i] = __uint_as_float(t);
    }
}

// ---------------------------------------------------------------------------
// Edge kernel: 128 edges/CTA, tf32 mma.sync 3-layer MLP, scatter-add output.
// 4 warps; warp w owns rows [32w, 32w+32). N=128 (16 n-tiles of 8).
// ---------------------------------------------------------------------------
__global__ void __launch_bounds__(128, 2)
edge_kernel(const float* __restrict__ x, const void* __restrict__ ei,
            const float* __restrict__ ea,
            const float* __restrict__ b1, const float* __restrict__ b2,
            const float* __restrict__ b3)
{
    extern __shared__ uint32_t smem[];
    uint32_t* sA = smem;               // 128 x AST (tf32 bits)
    uint32_t* sW = smem + 128 * AST;   // 64 x WST
    __shared__ int   sDst[TE];
    __shared__ float sBias[384];

    const int tid  = threadIdx.x;
    const int wid  = tid >> 5;
    const int lane = tid & 31;
    const int e0   = blockIdx.x * TE;

    int mySrc;
    {
        long long s, d;
        if (g_idx64) {
            const long long* p = (const long long*)ei;
            s = p[e0 + tid]; d = p[NE + e0 + tid];
        } else {
            const int* p = (const int*)ei;
            s = p[e0 + tid]; d = p[NE + e0 + tid];
        }
        mySrc = (int)s;
        sDst[tid] = (int)d;
        red1(&g_cnt[(int)d], 1.0f);
        sBias[tid]       = b1[tid];
        sBias[128 + tid] = b2[tid];
        sBias[256 + tid] = b3[tid];
    }
    __syncthreads();

    float acc0[16][4], acc1[16][4];
    #pragma unroll
    for (int nt = 0; nt < 16; nt++)
        #pragma unroll
        for (int j = 0; j < 4; j++) { acc0[nt][j] = 0.0f; acc1[nt][j] = 0.0f; }

    const int ar = wid * 32 + (lane >> 2);   // base A row for this lane
    const int kq = lane & 3;
    const int bn = lane >> 2;

    // ---- the 5 GEMM chunks: L1 = {dst, ea, src} (K=128 each), L2, L3 ----
    #pragma unroll 1
    for (int step = 0; step < 5; step++) {
        // -- fill sA --
        if (step < 3) {
            // gather chunk: 128 rows x 32 float4
            #pragma unroll 1
            for (int i = tid; i < 128 * 32; i += 128) {
                int r = i >> 5, q = i & 31;
                const float* srow;
                if (step == 1)      srow = ea + (size_t)(e0 + r) * DD;
                else if (step == 0) srow = x + (size_t)sDst[r] * DD;
                else                srow = x + (size_t)__shfl_sync(0xFFFFFFFFu, mySrc, 0) * DD * 0; // placeholder
                if (step == 2) {
                    // need src index per row; read from per-thread reg via smem-free path:
                    srow = x + (size_t)0;
                }
                float4 v;
                if (step == 2) {
                    // src gather handled below with sSrc-free trick: recompute index
                    // (fallthrough replaced)
                }
                v = *(const float4*)(srow + q * 4);
                uint4 t;
                t.x = f2tf(v.x); t.y = f2tf(v.y); t.z = f2tf(v.z); t.w = f2tf(v.w);
                *(uint4*)&sA[r * AST + q * 4] = t;
            }
        }
        // (see below — real code replaces this; kept structure simple)
        break;
    }

    // NOTE: the loop above is unrolled explicitly below for clarity/correctness.
    // ---- Layer 1 (3 chunks) + Layer 2 + Layer 3 ----
    __shared__ int sSrc[TE];
    sSrc[tid] = mySrc;
    __syncthreads();

    #pragma unroll 1
    for (int step = 0; step < 5; step++) {
        // fill sA: gather for steps 0-2; writeback handled at end of prev step for 3-4
        if (step < 3) {
            #pragma unroll 1
            for (int i = tid; i < 128 * 32; i += 128) {
                int r = i >> 5, q = i & 31;
                const float* srow;
                if (step == 1)      srow = ea + (size_t)(e0 + r) * DD;
                else if (step == 0) srow = x + (size_t)sDst[r] * DD;
                else                srow = x + (size_t)sSrc[r] * DD;
                float4 v = *(const float4*)(srow + q * 4);
                uint4 t;
                t.x = f2tf(v.x); t.y = f2tf(v.y); t.z = f2tf(v.z); t.w = f2tf(v.w);
                *(uint4*)&sA[r * AST + q * 4] = t;
            }
        }

        const int wrow = (step < 3) ? step * 128 : (step == 3 ? 384 : 512);

        // two K=64 halves
        #pragma unroll 1
        for (int h = 0; h < 2; h++) {
            // stage weights: 64 rows x WST
            {
                const float4* src4 = (const float4*)(g_Wpack + (size_t)(wrow + h * 64) * WST);
                float4* dst4 = (float4*)sW;
                #pragma unroll 1
                for (int i = tid; i < 64 * WST / 4; i += 128) dst4[i] = src4[i];
            }
            __syncthreads();

            #pragma unroll 1
            for (int ks = 0; ks < 8; ks++) {
                const int k0 = h * 64 + ks * 8;
                uint32_t a0[4], a1[4];
                a0[0] = sA[ar * AST + k0 + kq];
                a0[1] = sA[(ar + 8) * AST + k0 + kq];
                a0[2] = sA[ar * AST + k0 + kq + 4];
                a0[3] = sA[(ar + 8) * AST + k0 + kq + 4];
                a1[0] = sA[(ar + 16) * AST + k0 + kq];
                a1[1] = sA[(ar + 24) * AST + k0 + kq];
                a1[2] = sA[(ar + 16) * AST + k0 + kq + 4];
                a1[3] = sA[(ar + 24) * AST + k0 + kq + 4];
                const int bro = (ks * 8 + kq) * WST + bn;
                #pragma unroll
                for (int nt = 0; nt < 16; nt++) {
                    uint32_t b0 = sW[bro + nt * 8];
                    uint32_t b1v = sW[bro + 4 * WST + nt * 8];
                    mma8(acc0[nt], a0, b0, b1v);
                    mma8(acc1[nt], a1, b0, b1v);
                }
            }
            __syncthreads();
        }

        // end-of-layer actions
        if (step == 2 || step == 3) {
            // +bias, ReLU, write back to sA as tf32; zero acc
            const int boff = (step == 2) ? 0 : 128;
            const int cb = 2 * kq;
            #pragma unroll
            for (int nt = 0; nt < 16; nt++) {
                int c = nt * 8 + cb;
                float bv0 = sBias[boff + c], bv1 = sBias[boff + c + 1];
                sA[ar * AST + c]            = f2tf(fmaxf(acc0[nt][0] + bv0, 0.0f));
                sA[ar * AST + c + 1]        = f2tf(fmaxf(acc0[nt][1] + bv1, 0.0f));
                sA[(ar + 8) * AST + c]      = f2tf(fmaxf(acc0[nt][2] + bv0, 0.0f));
                sA[(ar + 8) * AST + c + 1]  = f2tf(fmaxf(acc0[nt][3] + bv1, 0.0f));
                sA[(ar + 16) * AST + c]     = f2tf(fmaxf(acc1[nt][0] + bv0, 0.0f));
                sA[(ar + 16) * AST + c + 1] = f2tf(fmaxf(acc1[nt][1] + bv1, 0.0f));
                sA[(ar + 24) * AST + c]     = f2tf(fmaxf(acc1[nt][2] + bv0, 0.0f));
                sA[(ar + 24) * AST + c + 1] = f2tf(fmaxf(acc1[nt][3] + bv1, 0.0f));
                #pragma unroll
                for (int j = 0; j < 4; j++) { acc0[nt][j] = 0.0f; acc1[nt][j] = 0.0f; }
            }
            __syncthreads();
        }
    }

    // ---- Epilogue: +b3, scatter-add messages ----
    {
        const int d0 = sDst[ar],      d1 = sDst[ar + 8];
        const int d2 = sDst[ar + 16], d3 = sDst[ar + 24];
        float* p0 = g_sums + (size_t)d0 * DD;
        float* p1 = g_sums + (size_t)d1 * DD;
        float* p2 = g_sums + (size_t)d2 * DD;
        float* p3 = g_sums + (size_t)d3 * DD;
        const int cb = 2 * kq;
        #pragma unroll
        for (int nt = 0; nt < 16; nt++) {
            int c = nt * 8 + cb;
            float bv0 = sBias[256 + c], bv1 = sBias[256 + c + 1];
            red2(p0 + c, acc0[nt][0] + bv0, acc0[nt][1] + bv1);
            red2(p1 + c, acc0[nt][2] + bv0, acc0[nt][3] + bv1);
            red2(p2 + c, acc1[nt][0] + bv0, acc1[nt][1] + bv1);
            red2(p3 + c, acc1[nt][2] + bv0, acc1[nt][3] + bv1);
        }
    }
}

// ---------------------------------------------------------------------------
// Node kernel: 8 nodes/block (256 threads). dh, LN1, FFN, LN2.
// ---------------------------------------------------------------------------
__device__ __forceinline__ float wredsum(float v) {
    #pragma unroll
    for (int o = 16; o > 0; o >>= 1) v += __shfl_xor_sync(0xFFFFFFFFu, v, o);
    return v;
}

__global__ void __launch_bounds__(256)
node_kernel(const float* __restrict__ x,
            const float* __restrict__ F1, const float* __restrict__ bf1,
            const float* __restrict__ F2, const float* __restrict__ bf2,
            const float* __restrict__ g0, const float* __restrict__ be0,
            const float* __restrict__ g1, const float* __restrict__ be1,
            float* __restrict__ out)
{
    const int t = threadIdx.x;
    const int w = t >> 5, lane = t & 31;
    const int n0 = blockIdx.x * 8;

    __shared__ float sH[8][128];
    __shared__ float sF[8][256];

    // Phase A: warp w -> node n0+w: z = x + sums/cnt; LN1 -> sH
    {
        const int n = n0 + w;
        float cnt = fmaxf(g_cnt[n], 1.0f);
        float4 xv = *(const float4*)&x[(size_t)n * DD + lane * 4];
        float4 sv = *(const float4*)&g_sums[(size_t)n * DD + lane * 4];
        float ic = 1.0f / cnt;
        float4 z = make_float4(xv.x + sv.x * ic, xv.y + sv.y * ic,
                               xv.z + sv.z * ic, xv.w + sv.w * ic);
        float s  = wredsum(z.x + z.y + z.z + z.w);
        float q  = wredsum(z.x * z.x + z.y * z.y + z.z * z.z + z.w * z.w);
        float mu = s * (1.0f / DD);
        float var = q * (1.0f / DD) - mu * mu;
        float rs = rsqrtf(var + 1e-6f);
        float4 gv = *(const float4*)&g0[lane * 4];
        float4 bv = *(const float4*)&be0[lane * 4];
        float4 hv;
        hv.x = (z.x - mu) * rs * gv.x + bv.x;
        hv.y = (z.y - mu) * rs * gv.y + bv.y;
        hv.z = (z.z - mu) * rs * gv.z + bv.z;
        hv.w = (z.w - mu) * rs * gv.w + bv.w;
        *(float4*)&sH[w][lane * 4] = hv;
    }
    __syncthreads();

    // Phase B: FFN1. group g=t>>6 handles nodes 2g,2g+1; cols c0=(t&63)*4.
    {
        const int g = t >> 6;
        const int i0 = 2 * g, i1 = 2 * g + 1;
        const int c = (t & 63) * 4;
        float4 a0 = *(const float4*)&bf1[c];
        float4 a1 = a0;
        #pragma unroll 4
        for (int k = 0; k < 128; k++) {
            float4 f = *(const float4*)&F1[(size_t)k * 256 + c];
            float h0 = sH[i0][k], h1 = sH[i1][k];
            a0.x += h0 * f.x; a0.y += h0 * f.y; a0.z += h0 * f.z; a0.w += h0 * f.w;
            a1.x += h1 * f.x; a1.y += h1 * f.y; a1.z += h1 * f.z; a1.w += h1 * f.w;
        }
        a0.x = fmaxf(a0.x, 0.0f); a0.y = fmaxf(a0.y, 0.0f);
        a0.z = fmaxf(a0.z, 0.0f); a0.w = fmaxf(a0.w, 0.0f);
        a1.x = fmaxf(a1.x, 0.0f); a1.y = fmaxf(a1.y, 0.0f);
        a1.z = fmaxf(a1.z, 0.0f); a1.w = fmaxf(a1.w, 0.0f);
        *(float4*)&sF[i0][c] = a0;
        *(float4*)&sF[i1][c] = a1;
    }
    __syncthreads();

    // Phase C: FFN2 + LN2. warp w -> node n0+w, cols lane*4..+3.
    {
        const int n = n0 + w;
        const int c = lane * 4;
        float4 o = *(const float4*)&bf2[c];
        #pragma unroll 4
        for (int k = 0; k < 256; k++) {
            float4 f = *(const float4*)&F2[(size_t)k * DD + c];
            float hk = sF[w][k];
            o.x += hk * f.x; o.y += hk * f.y; o.z += hk * f.z; o.w += hk * f.w;
        }
        float4 hv = *(const float4*)&sH[w][c];
        float4 y = make_float4(hv.x + o.x, hv.y + o.y, hv.z + o.z, hv.w + o.w);
        float s  = wredsum(y.x + y.y + y.z + y.w);
        float q  = wredsum(y.x * y.x + y.y * y.y + y.z * y.z + y.w * y.w);
        float mu = s * (1.0f / DD);
        float var = q * (1.0f / DD) - mu * mu;
        float rs = rsqrtf(var + 1e-6f);
        float4 gv = *(const float4*)&g1[c];
        float4 bv = *(const float4*)&be1[c];
        float4 r;
        r.x = (y.x - mu) * rs * gv.x + bv.x;
        r.y = (y.y - mu) * rs * gv.y + bv.y;
        r.z = (y.z - mu) * rs * gv.z + bv.z;
        r.w = (y.w - mu) * rs * gv.w + bv.w;
        *(float4*)&out[(size_t)n * DD + c] = r;
    }
}

// ---------------------------------------------------------------------------
extern "C" void kernel_launch(void* const* d_in, const int* in_sizes, int n_in,
                              void* d_out, int out_size) {
    const float* x   = (const float*)d_in[0];
    const void*  ei  = d_in[1];
    const float* ea  = (const float*)d_in[2];
    const float* W1  = (const float*)d_in[3];
    const float* b1  = (const float*)d_in[4];
    const float* W2  = (const float*)d_in[5];
    const float* b2  = (const float*)d_in[6];
    const float* W3  = (const float*)d_in[7];
    const float* b3  = (const float*)d_in[8];
    const float* F1  = (const float*)d_in[9];
    const float* bf1 = (const float*)d_in[10];
    const float* F2  = (const float*)d_in[11];
    const float* bf2 = (const float*)d_in[12];
    const float* g0  = (const float*)d_in[13];
    const float* be0 = (const float*)d_in[14];
    const float* g1  = (const float*)d_in[15];
    const float* be1 = (const float*)d_in[16];
    float* out = (float*)d_out;

    static int inited = 0;
    if (!inited) {
        cudaFuncSetAttribute(edge_kernel, cudaFuncAttributeMaxDynamicSharedMemorySize, EDGE_SMEM);
        inited = 1;
    }

    prep_kernel<<<5000, 256>>>((const unsigned*)ei, W1, W2, W3);
    edge_kernel<<<NTILES, 128, EDGE_SMEM>>>(x, ei, ea, b1, b2, b3);
    node_kernel<<<NN / 8, 256>>>(x, F1, bf1, F2, bf2, g0, be0, g1, be1, out);
}

// round 10
// speedup vs baseline: 2.2172x; 1.1821x over previous
#include <cuda_runtime.h>
#include <cuda_bf16.h>
#include <cstdint>

#define NN 10000
#define NE 640000
#define DD 128
#define TE 256                 // edges per CTA
#define NTILES (NE / TE)
#define AST 132                // sA row stride (floats)
#define WST 68                 // sW row stride (floats), 64 + 4 pad
#define EDGE_SMEM ((TE * AST + 128 * WST) * 4)   // 135168 + 34816 = 169984 B

__device__ float g_sums[NN * DD];
__device__ float g_cnt[NN];
__device__ int   g_idx64;
__device__ float g_Wpack[5 * 128 * 128];  // [chunk][n][k] tf32: W1(3) | W2 | W3

// ---------------- helpers ----------------
__device__ __forceinline__ uint32_t f2tf(float f) {
    uint32_t r;
    asm("cvt.rna.tf32.f32 %0, %1;" : "=r"(r) : "f"(f));
    return r;
}
__device__ __forceinline__ uint32_t smem_u32(const void* p) {
    uint32_t a;
    asm("{ .reg .u64 t; cvta.to.shared.u64 t, %1; cvt.u32.u64 %0, t; }" : "=r"(a) : "l"(p));
    return a;
}
__device__ __forceinline__ void mma8(float* d, const uint32_t* a, uint32_t b0, uint32_t b1) {
    asm volatile("mma.sync.aligned.m16n8k8.row.col.f32.tf32.tf32.f32 "
                 "{%0,%1,%2,%3}, {%4,%5,%6,%7}, {%8,%9}, {%0,%1,%2,%3};"
                 : "+f"(d[0]), "+f"(d[1]), "+f"(d[2]), "+f"(d[3])
                 : "r"(a[0]), "r"(a[1]), "r"(a[2]), "r"(a[3]), "r"(b0), "r"(b1));
}
#define LDSM4(r, a)                                                               \
    asm volatile("ldmatrix.sync.aligned.m8n8.x4.shared.b16 {%0,%1,%2,%3}, [%4];"  \
        : "=r"((r)[0]), "=r"((r)[1]), "=r"((r)[2]), "=r"((r)[3]) : "r"(a))
__device__ __forceinline__ void red2(float* addr, float a, float b) {
    asm volatile("red.global.add.v2.f32 [%0], {%1, %2};" :: "l"(addr), "f"(a), "f"(b) : "memory");
}
__device__ __forceinline__ void red1(float* addr, float a) {
    asm volatile("red.global.add.f32 [%0], %1;" :: "l"(addr), "f"(a) : "memory");
}

// ---------------------------------------------------------------------------
// Prep: zero scratch, sniff edge_index dtype, pack weights [chunk][n][k] tf32.
// g_Wpack[c][n][k]: c<3 -> W1[c*128+k][n]; c==3 -> W2[k][n]; c==4 -> W3[k][n].
// ---------------------------------------------------------------------------
__global__ void prep_kernel(const unsigned* ei_words,
                            const float* __restrict__ W1,
                            const float* __restrict__ W2,
                            const float* __restrict__ W3) {
    int i = blockIdx.x * 256 + threadIdx.x;
    if (i < NN * DD) g_sums[i] = 0.0f;
    if (i < NN)      g_cnt[i]  = 0.0f;
    if (i == 0) {
        int all0 = 1;
        #pragma unroll
        for (int k = 1; k < 64; k += 2) all0 &= (ei_words[k] == 0u);
        g_idx64 = all0;
    }
    if (i < 5 * 16384) {
        int c = i >> 14, j = i & 16383;
        int n = j >> 7, k = j & 127;
        float v;
        if (c < 3)       v = W1[(c * 128 + k) * DD + n];
        else if (c == 3) v = W2[k * DD + n];
        else             v = W3[k * DD + n];
        g_Wpack[i] = __uint_as_float(f2tf(v));
    }
}

// ---------------------------------------------------------------------------
// Edge kernel: 256 edges/CTA, 8 warps; warp w owns rows [32w, 32w+32).
// tf32 mma.sync m16n8k8, LDSM fragment loads, 3-layer MLP, scatter-add out.
// ---------------------------------------------------------------------------
__global__ void __launch_bounds__(256, 1)
edge_kernel(const float* __restrict__ x, const void* __restrict__ ei,
            const float* __restrict__ ea,
            const float* __restrict__ b1, const float* __restrict__ b2,
            const float* __restrict__ b3)
{
    extern __shared__ uint32_t smem[];
    uint32_t* sA = smem;               // 256 x AST (tf32 bits)
    uint32_t* sW = smem + TE * AST;    // 128 x WST (one 64-k half of a chunk)
    __shared__ int   sDst[TE];
    __shared__ int   sSrc[TE];
    __shared__ float sBias[384];

    const int tid  = threadIdx.x;
    const int wid  = tid >> 5;
    const int lane = tid & 31;
    const int e0   = blockIdx.x * TE;

    {
        long long s, d;
        if (g_idx64) {
            const long long* p = (const long long*)ei;
            s = p[e0 + tid]; d = p[NE + e0 + tid];
        } else {
            const int* p = (const int*)ei;
            s = p[e0 + tid]; d = p[NE + e0 + tid];
        }
        sSrc[tid] = (int)s;
        sDst[tid] = (int)d;
        red1(&g_cnt[(int)d], 1.0f);
        if (tid < 128) { sBias[tid] = b1[tid]; sBias[128 + tid] = b2[tid]; sBias[256 + tid] = b3[tid]; }
    }
    __syncthreads();

    const uint32_t sAb = smem_u32(sA);
    const uint32_t sWb = smem_u32(sW);

    // LDSM lane-address components
    const int sub = lane >> 3, lr = lane & 7;
    // A m-tile 0 (rows wid*32..+15): sub0=(+lr,k0) sub1=(+8+lr,k0) sub2=(+lr,k0+4) sub3=(+8+lr,k0+4)
    const uint32_t aAddr0 = sAb + (uint32_t)(((wid * 32 + (sub & 1) * 8 + lr) * AST + (sub >> 1) * 4) * 4);
    const uint32_t aAddr1 = aAddr0 + 16 * AST * 4;
    // B for n-tile pair p (n0=p*16): sub0=(n0+lr,k0) sub1=(n0+lr,k0+4) sub2=(n0+8+lr,k0) sub3=(n0+8+lr,k0+4)
    const uint32_t bAddr0 = sWb + (uint32_t)((((sub >> 1) * 8 + lr) * WST + (sub & 1) * 4) * 4);

    float acc0[16][4], acc1[16][4];
    #pragma unroll
    for (int nt = 0; nt < 16; nt++)
        #pragma unroll
        for (int j = 0; j < 4; j++) { acc0[nt][j] = 0.0f; acc1[nt][j] = 0.0f; }

    const int ar = wid * 32 + (lane >> 2);   // D-frag base row (acc0); acc1 = +16
    const int kq = lane & 3;

    #pragma unroll 1
    for (int step = 0; step < 5; step++) {
        // ---- fill sA (gather + tf32 convert) for L1 chunks ----
        if (step < 3) {
            #pragma unroll 1
            for (int i = tid; i < TE * 32; i += 256) {
                int r = i >> 5, q = i & 31;
                const float* srow;
                if (step == 1)      srow = ea + (size_t)(e0 + r) * DD;
                else if (step == 0) srow = x + (size_t)sDst[r] * DD;
                else                srow = x + (size_t)sSrc[r] * DD;
                float4 v = *(const float4*)(srow + q * 4);
                uint4 t;
                t.x = f2tf(v.x); t.y = f2tf(v.y); t.z = f2tf(v.z); t.w = f2tf(v.w);
                *(uint4*)&sA[r * AST + q * 4] = t;
            }
            __syncthreads();
        }

        const int chunk = (step < 3) ? step : (step == 3 ? 3 : 4);

        #pragma unroll 1
        for (int h = 0; h < 2; h++) {
            // stage W half: sW[n][0..63] = g_Wpack[chunk][n][h*64..+63]
            {
                const float* src = g_Wpack + (size_t)chunk * 16384 + h * 64;
                #pragma unroll 1
                for (int i = tid; i < 128 * 16; i += 256) {
                    int n = i >> 4, q = i & 15;
                    *(float4*)&sW[n * WST + q * 4] = *(const float4*)(src + (size_t)n * 128 + q * 4);
                }
            }
            __syncthreads();

            #pragma unroll 1
            for (int ks = 0; ks < 8; ks++) {
                const uint32_t ka = (uint32_t)((h * 64 + ks * 8) * 4);  // sA col byte offset
                const uint32_t kb = (uint32_t)(ks * 8 * 4);             // sW col byte offset
                uint32_t a0[4], a1[4];
                LDSM4(a0, aAddr0 + ka);
                LDSM4(a1, aAddr1 + ka);
                #pragma unroll
                for (int p = 0; p < 8; p++) {
                    uint32_t b[4];
                    LDSM4(b, bAddr0 + (uint32_t)(p * 16 * WST * 4) + kb);
                    mma8(acc0[2 * p],     a0, b[0], b[1]);
                    mma8(acc1[2 * p],     a1, b[0], b[1]);
                    mma8(acc0[2 * p + 1], a0, b[2], b[3]);
                    mma8(acc1[2 * p + 1], a1, b[2], b[3]);
                }
            }
            __syncthreads();
        }

        // ---- end of layer 1 / layer 2: +bias, ReLU, writeback, zero acc ----
        if (step == 2 || step == 3) {
            const int boff = (step == 2) ? 0 : 128;
            const int cb = 2 * kq;
            #pragma unroll
            for (int nt = 0; nt < 16; nt++) {
                int c = nt * 8 + cb;
                float bv0 = sBias[boff + c], bv1 = sBias[boff + c + 1];
                sA[ar * AST + c]            = f2tf(fmaxf(acc0[nt][0] + bv0, 0.0f));
                sA[ar * AST + c + 1]        = f2tf(fmaxf(acc0[nt][1] + bv1, 0.0f));
                sA[(ar + 8) * AST + c]      = f2tf(fmaxf(acc0[nt][2] + bv0, 0.0f));
                sA[(ar + 8) * AST + c + 1]  = f2tf(fmaxf(acc0[nt][3] + bv1, 0.0f));
                sA[(ar + 16) * AST + c]     = f2tf(fmaxf(acc1[nt][0] + bv0, 0.0f));
                sA[(ar + 16) * AST + c + 1] = f2tf(fmaxf(acc1[nt][1] + bv1, 0.0f));
                sA[(ar + 24) * AST + c]     = f2tf(fmaxf(acc1[nt][2] + bv0, 0.0f));
                sA[(ar + 24) * AST + c + 1] = f2tf(fmaxf(acc1[nt][3] + bv1, 0.0f));
                #pragma unroll
                for (int j = 0; j < 4; j++) { acc0[nt][j] = 0.0f; acc1[nt][j] = 0.0f; }
            }
            __syncthreads();
        }
    }

    // ---- Epilogue: +b3, scatter-add messages ----
    {
        const int d0 = sDst[ar],      d1 = sDst[ar + 8];
        const int d2 = sDst[ar + 16], d3 = sDst[ar + 24];
        float* p0 = g_sums + (size_t)d0 * DD;
        float* p1 = g_sums + (size_t)d1 * DD;
        float* p2 = g_sums + (size_t)d2 * DD;
        float* p3 = g_sums + (size_t)d3 * DD;
        const int cb = 2 * kq;
        #pragma unroll
        for (int nt = 0; nt < 16; nt++) {
            int c = nt * 8 + cb;
            float bv0 = sBias[256 + c], bv1 = sBias[256 + c + 1];
            red2(p0 + c, acc0[nt][0] + bv0, acc0[nt][1] + bv1);
            red2(p1 + c, acc0[nt][2] + bv0, acc0[nt][3] + bv1);
            red2(p2 + c, acc1[nt][0] + bv0, acc1[nt][1] + bv1);
            red2(p3 + c, acc1[nt][2] + bv0, acc1[nt][3] + bv1);
        }
    }
}

// ---------------------------------------------------------------------------
// Node kernel: 8 nodes/block (256 threads). dh, LN1, FFN, LN2.
// ---------------------------------------------------------------------------
__device__ __forceinline__ float wredsum(float v) {
    #pragma unroll
    for (int o = 16; o > 0; o >>= 1) v += __shfl_xor_sync(0xFFFFFFFFu, v, o);
    return v;
}

__global__ void __launch_bounds__(256)
node_kernel(const float* __restrict__ x,
            const float* __restrict__ F1, const float* __restrict__ bf1,
            const float* __restrict__ F2, const float* __restrict__ bf2,
            const float* __restrict__ g0, const float* __restrict__ be0,
            const float* __restrict__ g1, const float* __restrict__ be1,
            float* __restrict__ out)
{
    const int t = threadIdx.x;
    const int w = t >> 5, lane = t & 31;
    const int n0 = blockIdx.x * 8;

    __shared__ float sH[8][128];
    __shared__ float sF[8][256];

    {
        const int n = n0 + w;
        float cnt = fmaxf(g_cnt[n], 1.0f);
        float4 xv = *(const float4*)&x[(size_t)n * DD + lane * 4];
        float4 sv = *(const float4*)&g_sums[(size_t)n * DD + lane * 4];
        float ic = 1.0f / cnt;
        float4 z = make_float4(xv.x + sv.x * ic, xv.y + sv.y * ic,
                               xv.z + sv.z * ic, xv.w + sv.w * ic);
        float s  = wredsum(z.x + z.y + z.z + z.w);
        float q  = wredsum(z.x * z.x + z.y * z.y + z.z * z.z + z.w * z.w);
        float mu = s * (1.0f / DD);
        float var = q * (1.0f / DD) - mu * mu;
        float rs = rsqrtf(var + 1e-6f);
        float4 gv = *(const float4*)&g0[lane * 4];
        float4 bv = *(const float4*)&be0[lane * 4];
        float4 hv;
        hv.x = (z.x - mu) * rs * gv.x + bv.x;
        hv.y = (z.y - mu) * rs * gv.y + bv.y;
        hv.z = (z.z - mu) * rs * gv.z + bv.z;
        hv.w = (z.w - mu) * rs * gv.w + bv.w;
        *(float4*)&sH[w][lane * 4] = hv;
    }
    __syncthreads();

    {
        const int g = t >> 6;
        const int i0 = 2 * g, i1 = 2 * g + 1;
        const int c = (t & 63) * 4;
        float4 a0 = *(const float4*)&bf1[c];
        float4 a1 = a0;
        #pragma unroll 4
        for (int k = 0; k < 128; k++) {
            float4 f = *(const float4*)&F1[(size_t)k * 256 + c];
            float h0 = sH[i0][k], h1 = sH[i1][k];
            a0.x += h0 * f.x; a0.y += h0 * f.y; a0.z += h0 * f.z; a0.w += h0 * f.w;
            a1.x += h1 * f.x; a1.y += h1 * f.y; a1.z += h1 * f.z; a1.w += h1 * f.w;
        }
        a0.x = fmaxf(a0.x, 0.0f); a0.y = fmaxf(a0.y, 0.0f);
        a0.z = fmaxf(a0.z, 0.0f); a0.w = fmaxf(a0.w, 0.0f);
        a1.x = fmaxf(a1.x, 0.0f); a1.y = fmaxf(a1.y, 0.0f);
        a1.z = fmaxf(a1.z, 0.0f); a1.w = fmaxf(a1.w, 0.0f);
        *(float4*)&sF[i0][c] = a0;
        *(float4*)&sF[i1][c] = a1;
    }
    __syncthreads();

    {
        const int n = n0 + w;
        const int c = lane * 4;
        float4 o = *(const float4*)&bf2[c];
        #pragma unroll 4
        for (int k = 0; k < 256; k++) {
            float4 f = *(const float4*)&F2[(size_t)k * DD + c];
            float hk = sF[w][k];
            o.x += hk * f.x; o.y += hk * f.y; o.z += hk * f.z; o.w += hk * f.w;
        }
        float4 hv = *(const float4*)&sH[w][c];
        float4 y = make_float4(hv.x + o.x, hv.y + o.y, hv.z + o.z, hv.w + o.w);
        float s  = wredsum(y.x + y.y + y.z + y.w);
        float q  = wredsum(y.x * y.x + y.y * y.y + y.z * y.z + y.w * y.w);
        float mu = s * (1.0f / DD);
        float var = q * (1.0f / DD) - mu * mu;
        float rs = rsqrtf(var + 1e-6f);
        float4 gv = *(const float4*)&g1[c];
        float4 bv = *(const float4*)&be1[c];
        float4 r;
        r.x = (y.x - mu) * rs * gv.x + bv.x;
        r.y = (y.y - mu) * rs * gv.y + bv.y;
        r.z = (y.z - mu) * rs * gv.z + bv.z;
        r.w = (y.w - mu) * rs * gv.w + bv.w;
        *(float4*)&out[(size_t)n * DD + c] = r;
    }
}

// ---------------------------------------------------------------------------
extern "C" void kernel_launch(void* const* d_in, const int* in_sizes, int n_in,
                              void* d_out, int out_size) {
    const float* x   = (const float*)d_in[0];
    const void*  ei  = d_in[1];
    const float* ea  = (const float*)d_in[2];
    const float* W1  = (const float*)d_in[3];
    const float* b1  = (const float*)d_in[4];
    const float* W2  = (const float*)d_in[5];
    const float* b2  = (const float*)d_in[6];
    const float* W3  = (const float*)d_in[7];
    const float* b3  = (const float*)d_in[8];
    const float* F1  = (const float*)d_in[9];
    const float* bf1 = (const float*)d_in[10];
    const float* F2  = (const float*)d_in[11];
    const float* bf2 = (const float*)d_in[12];
    const float* g0  = (const float*)d_in[13];
    const float* be0 = (const float*)d_in[14];
    const float* g1  = (const float*)d_in[15];
    const float* be1 = (const float*)d_in[16];
    float* out = (float*)d_out;

    static int inited = 0;
    if (!inited) {
        cudaFuncSetAttribute(edge_kernel, cudaFuncAttributeMaxDynamicSharedMemorySize, EDGE_SMEM);
        inited = 1;
    }

    prep_kernel<<<5000, 256>>>((const unsigned*)ei, W1, W2, W3);
    edge_kernel<<<NTILES, 256, EDGE_SMEM>>>(x, ei, ea, b1, b2, b3);
    node_kernel<<<NN / 8, 256>>>(x, F1, bf1, F2, bf2, g0, be0, g1, be1, out);
}

// round 12
// speedup vs baseline: 3.4340x; 1.5488x over previous
#include <cuda_runtime.h>
#include <cuda_bf16.h>
#include <cstdint>

#define NN 10000
#define NE 640000
#define DD 128
#define TE 256                 // edges per CTA
#define NTILES (NE / TE)
#define ASTH 136               // sA row stride in halves (272 B)
#define WSTH 136               // sW row stride in halves (272 B)
#define A_BYTES (TE * ASTH * 2)          // 69632
#define W_BYTES (128 * WSTH * 2)         // 34816 per buffer
#define EDGE_SMEM (A_BYTES + 2 * W_BYTES)  // 139264

__device__ float g_sums[NN * DD];
__device__ float g_cnt[NN];
__device__ int   g_idx64;
__device__ __nv_bfloat16 g_Wpack[5 * 128 * 128];  // [chunk][n][k]: W1(3) | W2 | W3

// ---------------- helpers ----------------
__device__ __forceinline__ uint32_t smem_u32(const void* p) {
    uint32_t a;
    asm("{ .reg .u64 t; cvta.to.shared.u64 t, %1; cvt.u32.u64 %0, t; }" : "=r"(a) : "l"(p));
    return a;
}
__device__ __forceinline__ uint32_t bf2x(float hi, float lo) {
    uint32_t r;
    asm("cvt.rn.bf16x2.f32 %0, %1, %2;" : "=r"(r) : "f"(hi), "f"(lo));
    return r;
}
__device__ __forceinline__ void mma16(float* d, const uint32_t* a, uint32_t b0, uint32_t b1) {
    asm volatile("mma.sync.aligned.m16n8k16.row.col.f32.bf16.bf16.f32 "
                 "{%0,%1,%2,%3}, {%4,%5,%6,%7}, {%8,%9}, {%0,%1,%2,%3};"
                 : "+f"(d[0]), "+f"(d[1]), "+f"(d[2]), "+f"(d[3])
                 : "r"(a[0]), "r"(a[1]), "r"(a[2]), "r"(a[3]), "r"(b0), "r"(b1));
}
#define LDSM4(r, a)                                                               \
    asm volatile("ldmatrix.sync.aligned.m8n8.x4.shared.b16 {%0,%1,%2,%3}, [%4];"  \
        : "=r"((r)[0]), "=r"((r)[1]), "=r"((r)[2]), "=r"((r)[3]) : "r"(a))
__device__ __forceinline__ void cpasync16(uint32_t dst, const void* src) {
    asm volatile("cp.async.cg.shared.global [%0], [%1], 16;" :: "r"(dst), "l"(src) : "memory");
}
#define CP_COMMIT() asm volatile("cp.async.commit_group;" ::: "memory")
#define CP_WAIT(n)  asm volatile("cp.async.wait_group %0;" :: "n"(n) : "memory")
__device__ __forceinline__ void red2(float* addr, float a, float b) {
    asm volatile("red.global.add.v2.f32 [%0], {%1, %2};" :: "l"(addr), "f"(a), "f"(b) : "memory");
}
__device__ __forceinline__ void red1(float* addr, float a) {
    asm volatile("red.global.add.f32 [%0], %1;" :: "l"(addr), "f"(a) : "memory");
}

// ---------------------------------------------------------------------------
// Prep: zero scratch, sniff edge_index dtype, pack weights [chunk][n][k] bf16.
// ---------------------------------------------------------------------------
__global__ void prep_kernel(const unsigned* ei_words,
                            const float* __restrict__ W1,
                            const float* __restrict__ W2,
                            const float* __restrict__ W3) {
    int i = blockIdx.x * 256 + threadIdx.x;
    if (i < NN * DD) g_sums[i] = 0.0f;
    if (i < NN)      g_cnt[i]  = 0.0f;
    if (i == 0) {
        int all0 = 1;
        #pragma unroll
        for (int k = 1; k < 64; k += 2) all0 &= (ei_words[k] == 0u);
        g_idx64 = all0;
    }
    if (i < 5 * 16384) {
        int c = i >> 14, j = i & 16383;
        int n = j >> 7, k = j & 127;
        float v;
        if (c < 3)       v = W1[(c * 128 + k) * DD + n];
        else if (c == 3) v = W2[k * DD + n];
        else             v = W3[k * DD + n];
        g_Wpack[i] = __float2bfloat16_rn(v);
    }
}

// ---------------------------------------------------------------------------
// Edge kernel: 256 edges/CTA, 8 warps; warp w owns rows [32w, 32w+32).
// bf16 mma.sync m16n8k16, LDSM frags, cp.async double-buffered weights.
// ---------------------------------------------------------------------------
__global__ void __launch_bounds__(256, 1)
edge_kernel(const float* __restrict__ x, const void* __restrict__ ei,
            const float* __restrict__ ea,
            const float* __restrict__ b1, const float* __restrict__ b2,
            const float* __restrict__ b3)
{
    extern __shared__ uint16_t smem[];
    uint16_t* sA = smem;                          // 256 x ASTH halves
    const uint32_t sAb = smem_u32(sA);
    const uint32_t sW0 = sAb + A_BYTES;           // weight buffers
    __shared__ int   sDst[TE];
    __shared__ int   sSrc[TE];
    __shared__ float sBias[384];

    const int tid  = threadIdx.x;
    const int wid  = tid >> 5;
    const int lane = tid & 31;
    const int e0   = blockIdx.x * TE;

    {
        long long s, d;
        if (g_idx64) {
            const long long* p = (const long long*)ei;
            s = p[e0 + tid]; d = p[NE + e0 + tid];
        } else {
            const int* p = (const int*)ei;
            s = p[e0 + tid]; d = p[NE + e0 + tid];
        }
        sSrc[tid] = (int)s;
        sDst[tid] = (int)d;
        red1(&g_cnt[(int)d], 1.0f);
        if (tid < 128) { sBias[tid] = b1[tid]; sBias[128 + tid] = b2[tid]; sBias[256 + tid] = b3[tid]; }
    }

    // prefetch weight chunk 0 into buffer 0
    {
        const __nv_bfloat16* src = g_Wpack;
        #pragma unroll
        for (int r = 0; r < 8; r++) {
            int i = tid + r * 256;                // i in [0, 2048)
            int n = i >> 4, q = i & 15;
            cpasync16(sW0 + (uint32_t)(n * 272 + q * 16), src + (size_t)n * 128 + q * 8);
        }
        CP_COMMIT();
    }
    __syncthreads();

    // LDSM lane addressing
    const int sub = lane >> 3, lr = lane & 7;
    // A (m16n8k16): sub0=(r+lr, k0..7) sub1=(r+8+lr, k0..7) sub2=(r+lr, k8..15) sub3=(r+8+lr, k8..15)
    const uint32_t aAddr0 = sAb + (uint32_t)((wid * 32 + (sub & 1) * 8 + lr) * 272 + (sub >> 1) * 16);
    const uint32_t aAddr1 = aAddr0 + 16 * 272;
    // B: sub0=(n0+lr, k0..7) sub1=(n0+lr, k8..15) sub2=(n0+8+lr, k0..7) sub3=(n0+8+lr, k8..15)
    const uint32_t bOff   = (uint32_t)(((sub >> 1) * 8 + lr) * 272 + (sub & 1) * 16);

    float acc0[16][4], acc1[16][4];
    #pragma unroll
    for (int nt = 0; nt < 16; nt++)
        #pragma unroll
        for (int j = 0; j < 4; j++) { acc0[nt][j] = 0.0f; acc1[nt][j] = 0.0f; }

    const int ar = wid * 32 + (lane >> 2);   // D-frag base row (acc0); acc1 = +16
    const int kq = lane & 3;

    #pragma unroll 1
    for (int step = 0; step < 5; step++) {
        // ---- gather + fp32->bf16 convert into sA (layer-1 chunks) ----
        if (step < 3) {
            #pragma unroll 1
            for (int i = tid; i < TE * 32; i += 256) {
                int r = i >> 5, q = i & 31;
                const float* srow;
                if (step == 1)      srow = ea + (size_t)(e0 + r) * DD;
                else if (step == 0) srow = x + (size_t)sDst[r] * DD;
                else                srow = x + (size_t)sSrc[r] * DD;
                float4 v = *(const float4*)(srow + q * 4);
                uint2 t;
                t.x = bf2x(v.y, v.x);
                t.y = bf2x(v.w, v.z);
                *(uint2*)((char*)sA + r * 272 + q * 8) = t;
            }
        }

        // ---- prefetch next weight chunk into the other buffer ----
        if (step < 4) {
            const __nv_bfloat16* src = g_Wpack + (size_t)(step + 1) * 16384;
            const uint32_t dstb = sW0 + ((step + 1) & 1) * W_BYTES;
            #pragma unroll
            for (int r = 0; r < 8; r++) {
                int i = tid + r * 256;
                int n = i >> 4, q = i & 15;
                cpasync16(dstb + (uint32_t)(n * 272 + q * 16), src + (size_t)n * 128 + q * 8);
            }
            CP_COMMIT();
            CP_WAIT(1);   // current chunk (group step) complete; next may fly
        } else {
            CP_WAIT(0);
        }
        __syncthreads();

        // ---- MMA over full K=128 of this chunk ----
        const uint32_t bBase = sW0 + (step & 1) * W_BYTES + bOff;
        #pragma unroll 1
        for (int ks = 0; ks < 8; ks++) {
            const uint32_t ka = (uint32_t)(ks * 32);   // 16 halves = 32 B
            uint32_t a0[4], a1[4];
            LDSM4(a0, aAddr0 + ka);
            LDSM4(a1, aAddr1 + ka);
            #pragma unroll
            for (int p = 0; p < 8; p++) {
                uint32_t b[4];
                LDSM4(b, bBase + (uint32_t)(p * 16 * 272) + ka);
                mma16(acc0[2 * p],     a0, b[0], b[1]);
                mma16(acc1[2 * p],     a1, b[0], b[1]);
                mma16(acc0[2 * p + 1], a0, b[2], b[3]);
                mma16(acc1[2 * p + 1], a1, b[2], b[3]);
            }
        }

        // ---- end of layer 1 / layer 2: +bias, ReLU, writeback bf16, zero acc ----
        if (step == 2 || step == 3) {
            const int boff = (step == 2) ? 0 : 128;
            const int cb = 2 * kq;
            #pragma unroll
            for (int nt = 0; nt < 16; nt++) {
                int c = nt * 8 + cb;
                float bv0 = sBias[boff + c], bv1 = sBias[boff + c + 1];
                uint32_t v;
                v = bf2x(fmaxf(acc0[nt][1] + bv1, 0.0f), fmaxf(acc0[nt][0] + bv0, 0.0f));
                *(uint32_t*)((char*)sA + ar * 272 + 2 * c) = v;
                v = bf2x(fmaxf(acc0[nt][3] + bv1, 0.0f), fmaxf(acc0[nt][2] + bv0, 0.0f));
                *(uint32_t*)((char*)sA + (ar + 8) * 272 + 2 * c) = v;
                v = bf2x(fmaxf(acc1[nt][1] + bv1, 0.0f), fmaxf(acc1[nt][0] + bv0, 0.0f));
                *(uint32_t*)((char*)sA + (ar + 16) * 272 + 2 * c) = v;
                v = bf2x(fmaxf(acc1[nt][3] + bv1, 0.0f), fmaxf(acc1[nt][2] + bv0, 0.0f));
                *(uint32_t*)((char*)sA + (ar + 24) * 272 + 2 * c) = v;
                #pragma unroll
                for (int j = 0; j < 4; j++) { acc0[nt][j] = 0.0f; acc1[nt][j] = 0.0f; }
            }
        }
        __syncthreads();
    }

    // ---- Epilogue: +b3, scatter-add messages ----
    {
        const int d0 = sDst[ar],      d1 = sDst[ar + 8];
        const int d2 = sDst[ar + 16], d3 = sDst[ar + 24];
        float* p0 = g_sums + (size_t)d0 * DD;
        float* p1 = g_sums + (size_t)d1 * DD;
        float* p2 = g_sums + (size_t)d2 * DD;
        float* p3 = g_sums + (size_t)d3 * DD;
        const int cb = 2 * kq;
        #pragma unroll
        for (int nt = 0; nt < 16; nt++) {
            int c = nt * 8 + cb;
            float bv0 = sBias[256 + c], bv1 = sBias[256 + c + 1];
            red2(p0 + c, acc0[nt][0] + bv0, acc0[nt][1] + bv1);
            red2(p1 + c, acc0[nt][2] + bv0, acc0[nt][3] + bv1);
            red2(p2 + c, acc1[nt][0] + bv0, acc1[nt][1] + bv1);
            red2(p3 + c, acc1[nt][2] + bv0, acc1[nt][3] + bv1);
        }
    }
}

// ---------------------------------------------------------------------------
// Node kernel: 8 nodes/block (256 threads). dh, LN1, FFN, LN2.
// ---------------------------------------------------------------------------
__device__ __forceinline__ float wredsum(float v) {
    #pragma unroll
    for (int o = 16; o > 0; o >>= 1) v += __shfl_xor_sync(0xFFFFFFFFu, v, o);
    return v;
}

__global__ void __launch_bounds__(256)
node_kernel(const float* __restrict__ x,
            const float* __restrict__ F1, const float* __restrict__ bf1,
            const float* __restrict__ F2, const float* __restrict__ bf2,
            const float* __restrict__ g0, const float* __restrict__ be0,
            const float* __restrict__ g1, const float* __restrict__ be1,
            float* __restrict__ out)
{
    const int t = threadIdx.x;
    const int w = t >> 5, lane = t & 31;
    const int n0 = blockIdx.x * 8;

    __shared__ float sH[8][128];
    __shared__ float sF[8][256];

    {
        const int n = n0 + w;
        float cnt = fmaxf(g_cnt[n], 1.0f);
        float4 xv = *(const float4*)&x[(size_t)n * DD + lane * 4];
        float4 sv = *(const float4*)&g_sums[(size_t)n * DD + lane * 4];
        float ic = 1.0f / cnt;
        float4 z = make_float4(xv.x + sv.x * ic, xv.y + sv.y * ic,
                               xv.z + sv.z * ic, xv.w + sv.w * ic);
        float s  = wredsum(z.x + z.y + z.z + z.w);
        float q  = wredsum(z.x * z.x + z.y * z.y + z.z * z.z + z.w * z.w);
        float mu = s * (1.0f / DD);
        float var = q * (1.0f / DD) - mu * mu;
        float rs = rsqrtf(var + 1e-6f);
        float4 gv = *(const float4*)&g0[lane * 4];
        float4 bv = *(const float4*)&be0[lane * 4];
        float4 hv;
        hv.x = (z.x - mu) * rs * gv.x + bv.x;
        hv.y = (z.y - mu) * rs * gv.y + bv.y;
        hv.z = (z.z - mu) * rs * gv.z + bv.z;
        hv.w = (z.w - mu) * rs * gv.w + bv.w;
        *(float4*)&sH[w][lane * 4] = hv;
    }
    __syncthreads();

    {
        const int g = t >> 6;
        const int i0 = 2 * g, i1 = 2 * g + 1;
        const int c = (t & 63) * 4;
        float4 a0 = *(const float4*)&bf1[c];
        float4 a1 = a0;
        #pragma unroll 4
        for (int k = 0; k < 128; k++) {
            float4 f = *(const float4*)&F1[(size_t)k * 256 + c];
            float h0 = sH[i0][k], h1 = sH[i1][k];
            a0.x += h0 * f.x; a0.y += h0 * f.y; a0.z += h0 * f.z; a0.w += h0 * f.w;
            a1.x += h1 * f.x; a1.y += h1 * f.y; a1.z += h1 * f.z; a1.w += h1 * f.w;
        }
        a0.x = fmaxf(a0.x, 0.0f); a0.y = fmaxf(a0.y, 0.0f);
        a0.z = fmaxf(a0.z, 0.0f); a0.w = fmaxf(a0.w, 0.0f);
        a1.x = fmaxf(a1.x, 0.0f); a1.y = fmaxf(a1.y, 0.0f);
        a1.z = fmaxf(a1.z, 0.0f); a1.w = fmaxf(a1.w, 0.0f);
        *(float4*)&sF[i0][c] = a0;
        *(float4*)&sF[i1][c] = a1;
    }
    __syncthreads();

    {
        const int n = n0 + w;
        const int c = lane * 4;
        float4 o = *(const float4*)&bf2[c];
        #pragma unroll 4
        for (int k = 0; k < 256; k++) {
            float4 f = *(const float4*)&F2[(size_t)k * DD + c];
            float hk = sF[w][k];
            o.x += hk * f.x; o.y += hk * f.y; o.z += hk * f.z; o.w += hk * f.w;
        }
        float4 hv = *(const float4*)&sH[w][c];
        float4 y = make_float4(hv.x + o.x, hv.y + o.y, hv.z + o.z, hv.w + o.w);
        float s  = wredsum(y.x + y.y + y.z + y.w);
        float q  = wredsum(y.x * y.x + y.y * y.y + y.z * y.z + y.w * y.w);
        float mu = s * (1.0f / DD);
        float var = q * (1.0f / DD) - mu * mu;
        float rs = rsqrtf(var + 1e-6f);
        float4 gv = *(const float4*)&g1[c];
        float4 bv = *(const float4*)&be1[c];
        float4 r;
        r.x = (y.x - mu) * rs * gv.x + bv.x;
        r.y = (y.y - mu) * rs * gv.y + bv.y;
        r.z = (y.z - mu) * rs * gv.z + bv.z;
        r.w = (y.w - mu) * rs * gv.w + bv.w;
        *(float4*)&out[(size_t)n * DD + c] = r;
    }
}

// ---------------------------------------------------------------------------
extern "C" void kernel_launch(void* const* d_in, const int* in_sizes, int n_in,
                              void* d_out, int out_size) {
    const float* x   = (const float*)d_in[0];
    const void*  ei  = d_in[1];
    const float* ea  = (const float*)d_in[2];
    const float* W1  = (const float*)d_in[3];
    const float* b1  = (const float*)d_in[4];
    const float* W2  = (const float*)d_in[5];
    const float* b2  = (const float*)d_in[6];
    const float* W3  = (const float*)d_in[7];
    const float* b3  = (const float*)d_in[8];
    const float* F1  = (const float*)d_in[9];
    const float* bf1 = (const float*)d_in[10];
    const float* F2  = (const float*)d_in[11];
    const float* bf2 = (const float*)d_in[12];
    const float* g0  = (const float*)d_in[13];
    const float* be0 = (const float*)d_in[14];
    const float* g1  = (const float*)d_in[15];
    const float* be1 = (const float*)d_in[16];
    float* out = (float*)d_out;

    static int inited = 0;
    if (!inited) {
        cudaFuncSetAttribute(edge_kernel, cudaFuncAttributeMaxDynamicSharedMemorySize, EDGE_SMEM);
        inited = 1;
    }

    prep_kernel<<<5000, 256>>>((const unsigned*)ei, W1, W2, W3);
    edge_kernel<<<NTILES, 256, EDGE_SMEM>>>(x, ei, ea, b1, b2, b3);
    node_kernel<<<NN / 8, 256>>>(x, F1, bf1, F2, bf2, g0, be0, g1, be1, out);
}

// round 15
// speedup vs baseline: 5.6219x; 1.6371x over previous
#include <cuda_runtime.h>
#include <cuda_bf16.h>
#include <cstdint>

#define NN 10000
#define NE 640000
#define DD 128
#define TE 256                 // edges per CTA
#define NTILES (NE / TE)
#define ASTH 136               // sA row stride in halves (272 B)
#define WSTH 136               // sW row stride in halves (272 B)
#define A_BYTES (TE * ASTH * 2)          // 69632
#define W_BYTES (128 * WSTH * 2)         // 34816 per buffer
#define EDGE_SMEM (A_BYTES + 2 * W_BYTES)  // 139264

__device__ float g_sums[NN * DD];
__device__ float g_cnt[NN];
__device__ int   g_idx64;
__device__ __nv_bfloat16 g_Wpack[5 * 128 * 128];  // [chunk][n][k]: W1(3) | W2 | W3

// ---------------- helpers ----------------
__device__ __forceinline__ uint32_t smem_u32(const void* p) {
    uint32_t a;
    asm("{ .reg .u64 t; cvta.to.shared.u64 t, %1; cvt.u32.u64 %0, t; }" : "=r"(a) : "l"(p));
    return a;
}
__device__ __forceinline__ uint32_t bf2x(float hi, float lo) {
    uint32_t r;
    asm("cvt.rn.bf16x2.f32 %0, %1, %2;" : "=r"(r) : "f"(hi), "f"(lo));
    return r;
}
__device__ __forceinline__ void mma16(float* d, const uint32_t* a, uint32_t b0, uint32_t b1) {
    asm volatile("mma.sync.aligned.m16n8k16.row.col.f32.bf16.bf16.f32 "
                 "{%0,%1,%2,%3}, {%4,%5,%6,%7}, {%8,%9}, {%0,%1,%2,%3};"
                 : "+f"(d[0]), "+f"(d[1]), "+f"(d[2]), "+f"(d[3])
                 : "r"(a[0]), "r"(a[1]), "r"(a[2]), "r"(a[3]), "r"(b0), "r"(b1));
}
#define LDSM4(r, a)                                                               \
    asm volatile("ldmatrix.sync.aligned.m8n8.x4.shared.b16 {%0,%1,%2,%3}, [%4];"  \
        : "=r"((r)[0]), "=r"((r)[1]), "=r"((r)[2]), "=r"((r)[3]) : "r"(a))
__device__ __forceinline__ void cpasync16(uint32_t dst, const void* src) {
    asm volatile("cp.async.cg.shared.global [%0], [%1], 16;" :: "r"(dst), "l"(src) : "memory");
}
#define CP_COMMIT() asm volatile("cp.async.commit_group;" ::: "memory")
#define CP_WAIT(n)  asm volatile("cp.async.wait_group %0;" :: "n"(n) : "memory")
__device__ __forceinline__ void red2(float* addr, float a, float b) {
    asm volatile("red.global.add.v2.f32 [%0], {%1, %2};" :: "l"(addr), "f"(a), "f"(b) : "memory");
}
__device__ __forceinline__ void red1(float* addr, float a) {
    asm volatile("red.global.add.f32 [%0], %1;" :: "l"(addr), "f"(a) : "memory");
}

// ---------------------------------------------------------------------------
// Prep: zero scratch, sniff edge_index dtype, pack weights [chunk][n][k] bf16.
// ---------------------------------------------------------------------------
__global__ void prep_kernel(const unsigned* ei_words,
                            const float* __restrict__ W1,
                            const float* __restrict__ W2,
                            const float* __restrict__ W3) {
    int i = blockIdx.x * 256 + threadIdx.x;
    if (i < NN * DD) g_sums[i] = 0.0f;
    if (i < NN)      g_cnt[i]  = 0.0f;
    if (i == 0) {
        int all0 = 1;
        #pragma unroll
        for (int k = 1; k < 64; k += 2) all0 &= (ei_words[k] == 0u);
        g_idx64 = all0;
    }
    if (i < 5 * 16384) {
        int c = i >> 14, j = i & 16383;
        int n = j >> 7, k = j & 127;
        float v;
        if (c < 3)       v = W1[(c * 128 + k) * DD + n];
        else if (c == 3) v = W2[k * DD + n];
        else             v = W3[k * DD + n];
        g_Wpack[i] = __float2bfloat16_rn(v);
    }
}

// ---------------------------------------------------------------------------
// Edge kernel: 256 edges/CTA, 8 warps; warp w owns rows [32w, 32w+32).
// bf16 mma.sync m16n8k16, LDSM frags, cp.async weights, MLP-8 batched gather.
// ---------------------------------------------------------------------------
__global__ void __launch_bounds__(256, 1)
edge_kernel(const float* __restrict__ x, const void* __restrict__ ei,
            const float* __restrict__ ea,
            const float* __restrict__ b1, const float* __restrict__ b2,
            const float* __restrict__ b3)
{
    extern __shared__ uint16_t smem[];
    uint16_t* sA = smem;                          // 256 x ASTH halves
    const uint32_t sAb = smem_u32(sA);
    const uint32_t sW0 = sAb + A_BYTES;           // weight buffers
    __shared__ int   sDst[TE];
    __shared__ int   sSrc[TE];
    __shared__ float sBias[384];

    const int tid  = threadIdx.x;
    const int wid  = tid >> 5;
    const int lane = tid & 31;
    const int e0   = blockIdx.x * TE;

    {
        long long s, d;
        if (g_idx64) {
            const long long* p = (const long long*)ei;
            s = p[e0 + tid]; d = p[NE + e0 + tid];
        } else {
            const int* p = (const int*)ei;
            s = p[e0 + tid]; d = p[NE + e0 + tid];
        }
        sSrc[tid] = (int)s;
        sDst[tid] = (int)d;
        red1(&g_cnt[(int)d], 1.0f);
        if (tid < 128) { sBias[tid] = b1[tid]; sBias[128 + tid] = b2[tid]; sBias[256 + tid] = b3[tid]; }
    }

    // prefetch weight chunk 0 into buffer 0
    {
        const __nv_bfloat16* src = g_Wpack;
        #pragma unroll
        for (int r = 0; r < 8; r++) {
            int i = tid + r * 256;                // i in [0, 2048)
            int n = i >> 4, q = i & 15;
            cpasync16(sW0 + (uint32_t)(n * 272 + q * 16), src + (size_t)n * 128 + q * 8);
        }
        CP_COMMIT();
    }
    __syncthreads();

    // LDSM lane addressing
    const int sub = lane >> 3, lr = lane & 7;
    const uint32_t aAddr0 = sAb + (uint32_t)((wid * 32 + (sub & 1) * 8 + lr) * 272 + (sub >> 1) * 16);
    const uint32_t aAddr1 = aAddr0 + 16 * 272;
    const uint32_t bOff   = (uint32_t)(((sub >> 1) * 8 + lr) * 272 + (sub & 1) * 16);

    float acc0[16][4], acc1[16][4];
    #pragma unroll
    for (int nt = 0; nt < 16; nt++)
        #pragma unroll
        for (int j = 0; j < 4; j++) { acc0[nt][j] = 0.0f; acc1[nt][j] = 0.0f; }

    const int ar = wid * 32 + (lane >> 2);   // D-frag base row (acc0); acc1 = +16
    const int kq = lane & 3;

    #pragma unroll 1
    for (int step = 0; step < 5; step++) {
        // ---- gather + fp32->bf16 convert into sA, batched for MLP=8 ----
        // item i = tid + j*256 -> row r = wid + 8j, col-quad q = lane (const)
        if (step < 3) {
            #pragma unroll 1
            for (int jb = 0; jb < 4; jb++) {
                float4 v[8];
                #pragma unroll
                for (int u = 0; u < 8; u++) {
                    int r = wid + (jb * 8 + u) * 8;
                    const float* srow;
                    if (step == 1)      srow = ea + (size_t)(e0 + r) * DD;
                    else if (step == 0) srow = x + (size_t)sDst[r] * DD;
                    else                srow = x + (size_t)sSrc[r] * DD;
                    v[u] = *(const float4*)(srow + lane * 4);
                }
                #pragma unroll
                for (int u = 0; u < 8; u++) {
                    int r = wid + (jb * 8 + u) * 8;
                    uint2 t;
                    t.x = bf2x(v[u].y, v[u].x);
                    t.y = bf2x(v[u].w, v[u].z);
                    *(uint2*)((char*)sA + r * 272 + lane * 8) = t;
                }
            }
        }

        // ---- prefetch next weight chunk into the other buffer ----
        if (step < 4) {
            const __nv_bfloat16* src = g_Wpack + (size_t)(step + 1) * 16384;
            const uint32_t dstb = sW0 + ((step + 1) & 1) * W_BYTES;
            #pragma unroll
            for (int r = 0; r < 8; r++) {
                int i = tid + r * 256;
                int n = i >> 4, q = i & 15;
                cpasync16(dstb + (uint32_t)(n * 272 + q * 16), src + (size_t)n * 128 + q * 8);
            }
            CP_COMMIT();
            CP_WAIT(1);   // current chunk complete; next may fly
        } else {
            CP_WAIT(0);
        }
        __syncthreads();

        // ---- MMA over full K=128 of this chunk ----
        const uint32_t bBase = sW0 + (step & 1) * W_BYTES + bOff;
        #pragma unroll 1
        for (int ks = 0; ks < 8; ks++) {
            const uint32_t ka = (uint32_t)(ks * 32);   // 16 halves = 32 B
            uint32_t a0[4], a1[4];
            LDSM4(a0, aAddr0 + ka);
            LDSM4(a1, aAddr1 + ka);
            #pragma unroll
            for (int p = 0; p < 8; p++) {
                uint32_t b[4];
                LDSM4(b, bBase + (uint32_t)(p * 16 * 272) + ka);
                mma16(acc0[2 * p],     a0, b[0], b[1]);
                mma16(acc1[2 * p],     a1, b[0], b[1]);
                mma16(acc0[2 * p + 1], a0, b[2], b[3]);
                mma16(acc1[2 * p + 1], a1, b[2], b[3]);
            }
        }

        // ---- end of layer 1 / layer 2: +bias, ReLU, writeback bf16, zero acc ----
        if (step == 2 || step == 3) {
            const int boff = (step == 2) ? 0 : 128;
            const int cb = 2 * kq;
            #pragma unroll
            for (int nt = 0; nt < 16; nt++) {
                int c = nt * 8 + cb;
                float bv0 = sBias[boff + c], bv1 = sBias[boff + c + 1];
                uint32_t v;
                v = bf2x(fmaxf(acc0[nt][1] + bv1, 0.0f), fmaxf(acc0[nt][0] + bv0, 0.0f));
                *(uint32_t*)((char*)sA + ar * 272 + 2 * c) = v;
                v = bf2x(fmaxf(acc0[nt][3] + bv1, 0.0f), fmaxf(acc0[nt][2] + bv0, 0.0f));
                *(uint32_t*)((char*)sA + (ar + 8) * 272 + 2 * c) = v;
                v = bf2x(fmaxf(acc1[nt][1] + bv1, 0.0f), fmaxf(acc1[nt][0] + bv0, 0.0f));
                *(uint32_t*)((char*)sA + (ar + 16) * 272 + 2 * c) = v;
                v = bf2x(fmaxf(acc1[nt][3] + bv1, 0.0f), fmaxf(acc1[nt][2] + bv0, 0.0f));
                *(uint32_t*)((char*)sA + (ar + 24) * 272 + 2 * c) = v;
                #pragma unroll
                for (int j = 0; j < 4; j++) { acc0[nt][j] = 0.0f; acc1[nt][j] = 0.0f; }
            }
        }
        __syncthreads();
    }

    // ---- Epilogue: +b3, scatter-add messages ----
    {
        const int d0 = sDst[ar],      d1 = sDst[ar + 8];
        const int d2 = sDst[ar + 16], d3 = sDst[ar + 24];
        float* p0 = g_sums + (size_t)d0 * DD;
        float* p1 = g_sums + (size_t)d1 * DD;
        float* p2 = g_sums + (size_t)d2 * DD;
        float* p3 = g_sums + (size_t)d3 * DD;
        const int cb = 2 * kq;
        #pragma unroll
        for (int nt = 0; nt < 16; nt++) {
            int c = nt * 8 + cb;
            float bv0 = sBias[256 + c], bv1 = sBias[256 + c + 1];
            red2(p0 + c, acc0[nt][0] + bv0, acc0[nt][1] + bv1);
            red2(p1 + c, acc0[nt][2] + bv0, acc0[nt][3] + bv1);
            red2(p2 + c, acc1[nt][0] + bv0, acc1[nt][1] + bv1);
            red2(p3 + c, acc1[nt][2] + bv0, acc1[nt][3] + bv1);
        }
    }
}

// ---------------------------------------------------------------------------
// Node kernel: 16 nodes/block (512 threads). dh, LN1, FFN, LN2.
// ---------------------------------------------------------------------------
__device__ __forceinline__ float wredsum(float v) {
    #pragma unroll
    for (int o = 16; o > 0; o >>= 1) v += __shfl_xor_sync(0xFFFFFFFFu, v, o);
    return v;
}

__global__ void __launch_bounds__(512)
node_kernel(const float* __restrict__ x,
            const float* __restrict__ F1, const float* __restrict__ bf1,
            const float* __restrict__ F2, const float* __restrict__ bf2,
            const float* __restrict__ g0, const float* __restrict__ be0,
            const float* __restrict__ g1, const float* __restrict__ be1,
            float* __restrict__ out)
{
    const int t = threadIdx.x;
    const int w = t >> 5, lane = t & 31;
    const int n0 = blockIdx.x * 16;

    __shared__ float sH[16][128];
    __shared__ float sF[16][256];

    // Phase A: warp w -> node n0+w: z = x + sums/cnt; LN1 -> sH
    {
        const int n = n0 + w;
        float cnt = fmaxf(g_cnt[n], 1.0f);
        float4 xv = *(const float4*)&x[(size_t)n * DD + lane * 4];
        float4 sv = *(const float4*)&g_sums[(size_t)n * DD + lane * 4];
        float ic = 1.0f / cnt;
        float4 z = make_float4(xv.x + sv.x * ic, xv.y + sv.y * ic,
                               xv.z + sv.z * ic, xv.w + sv.w * ic);
        float s  = wredsum(z.x + z.y + z.z + z.w);
        float q  = wredsum(z.x * z.x + z.y * z.y + z.z * z.z + z.w * z.w);
        float mu = s * (1.0f / DD);
        float var = q * (1.0f / DD) - mu * mu;
        float rs = rsqrtf(var + 1e-6f);
        float4 gv = *(const float4*)&g0[lane * 4];
        float4 bv = *(const float4*)&be0[lane * 4];
        float4 hv;
        hv.x = (z.x - mu) * rs * gv.x + bv.x;
        hv.y = (z.y - mu) * rs * gv.y + bv.y;
        hv.z = (z.z - mu) * rs * gv.z + bv.z;
        hv.w = (z.w - mu) * rs * gv.w + bv.w;
        *(float4*)&sH[w][lane * 4] = hv;
    }
    __syncthreads();

    // Phase B: FFN1. group g=t>>6 (8 groups) handles nodes 2g, 2g+1.
    {
        const int g = t >> 6;
        const int i0 = 2 * g, i1 = 2 * g + 1;
        const int c = (t & 63) * 4;
        float4 a0 = *(const float4*)&bf1[c];
        float4 a1 = a0;
        #pragma unroll 4
        for (int k = 0; k < 128; k++) {
            float4 f = *(const float4*)&F1[(size_t)k * 256 + c];
            float h0 = sH[i0][k], h1 = sH[i1][k];
            a0.x += h0 * f.x; a0.y += h0 * f.y; a0.z += h0 * f.z; a0.w += h0 * f.w;
            a1.x += h1 * f.x; a1.y += h1 * f.y; a1.z += h1 * f.z; a1.w += h1 * f.w;
        }
        a0.x = fmaxf(a0.x, 0.0f); a0.y = fmaxf(a0.y, 0.0f);
        a0.z = fmaxf(a0.z, 0.0f); a0.w = fmaxf(a0.w, 0.0f);
        a1.x = fmaxf(a1.x, 0.0f); a1.y = fmaxf(a1.y, 0.0f);
        a1.z = fmaxf(a1.z, 0.0f); a1.w = fmaxf(a1.w, 0.0f);
        *(float4*)&sF[i0][c] = a0;
        *(float4*)&sF[i1][c] = a1;
    }
    __syncthreads();

    // Phase C: FFN2 + LN2. warp w -> node n0+w, cols lane*4..+3.
    {
        const int n = n0 + w;
        const int c = lane * 4;
        float4 o = *(const float4*)&bf2[c];
        #pragma unroll 4
        for (int k = 0; k < 256; k++) {
            float4 f = *(const float4*)&F2[(size_t)k * DD + c];
            float hk = sF[w][k];
            o.x += hk * f.x; o.y += hk * f.y; o.z += hk * f.z; o.w += hk * f.w;
        }
        float4 hv = *(const float4*)&sH[w][c];
        float4 y = make_float4(hv.x + o.x, hv.y + o.y, hv.z + o.z, hv.w + o.w);
        float s  = wredsum(y.x + y.y + y.z + y.w);
        float q  = wredsum(y.x * y.x + y.y * y.y + y.z * y.z + y.w * y.w);
        float mu = s * (1.0f / DD);
        float var = q * (1.0f / DD) - mu * mu;
        float rs = rsqrtf(var + 1e-6f);
        float4 gv = *(const float4*)&g1[c];
        float4 bv = *(const float4*)&be1[c];
        float4 r;
        r.x = (y.x - mu) * rs * gv.x + bv.x;
        r.y = (y.y - mu) * rs * gv.y + bv.y;
        r.z = (y.z - mu) * rs * gv.z + bv.z;
        r.w = (y.w - mu) * rs * gv.w + bv.w;
        *(float4*)&out[(size_t)n * DD + c] = r;
    }
}

// ---------------------------------------------------------------------------
extern "C" void kernel_launch(void* const* d_in, const int* in_sizes, int n_in,
                              void* d_out, int out_size) {
    const float* x   = (const float*)d_in[0];
    const void*  ei  = d_in[1];
    const float* ea  = (const float*)d_in[2];
    const float* W1  = (const float*)d_in[3];
    const float* b1  = (const float*)d_in[4];
    const float* W2  = (const float*)d_in[5];
    const float* b2  = (const float*)d_in[6];
    const float* W3  = (const float*)d_in[7];
    const float* b3  = (const float*)d_in[8];
    const float* F1  = (const float*)d_in[9];
    const float* bf1 = (const float*)d_in[10];
    const float* F2  = (const float*)d_in[11];
    const float* bf2 = (const float*)d_in[12];
    const float* g0  = (const float*)d_in[13];
    const float* be0 = (const float*)d_in[14];
    const float* g1  = (const float*)d_in[15];
    const float* be1 = (const float*)d_in[16];
    float* out = (float*)d_out;

    static int inited = 0;
    if (!inited) {
        cudaFuncSetAttribute(edge_kernel, cudaFuncAttributeMaxDynamicSharedMemorySize, EDGE_SMEM);
        inited = 1;
    }

    prep_kernel<<<5000, 256>>>((const unsigned*)ei, W1, W2, W3);
    edge_kernel<<<NTILES, 256, EDGE_SMEM>>>(x, ei, ea, b1, b2, b3);
    node_kernel<<<NN / 16, 512>>>(x, F1, bf1, F2, bf2, g0, be0, g1, be1, out);
}

// round 16
// speedup vs baseline: 5.8623x; 1.0428x over previous
#include <cuda_runtime.h>
#include <cuda_bf16.h>
#include <cstdint>

#define NN 10000
#define NE 640000
#define DD 128
#define TE 128                 // edges per CTA
#define NTILES (NE / TE)
#define A_BYTES (TE * 272)               // 34816
#define W_BYTES (128 * 272)              // 34816 per buffer
#define EDGE_SMEM (A_BYTES + 2 * W_BYTES)  // 104448 -> occupancy 2

__device__ float g_sums[NN * DD];
__device__ float g_cnt[NN];
__device__ int   g_idx64;
__device__ __nv_bfloat16 g_Wpack[5 * 128 * 128];  // [chunk][n][k]: W1(3) | W2 | W3

// ---------------- helpers ----------------
__device__ __forceinline__ uint32_t smem_u32(const void* p) {
    uint32_t a;
    asm("{ .reg .u64 t; cvta.to.shared.u64 t, %1; cvt.u32.u64 %0, t; }" : "=r"(a) : "l"(p));
    return a;
}
__device__ __forceinline__ uint32_t bf2x(float hi, float lo) {
    uint32_t r;
    asm("cvt.rn.bf16x2.f32 %0, %1, %2;" : "=r"(r) : "f"(hi), "f"(lo));
    return r;
}
__device__ __forceinline__ void mma16(float* d, const uint32_t* a, uint32_t b0, uint32_t b1) {
    asm volatile("mma.sync.aligned.m16n8k16.row.col.f32.bf16.bf16.f32 "
                 "{%0,%1,%2,%3}, {%4,%5,%6,%7}, {%8,%9}, {%0,%1,%2,%3};"
                 : "+f"(d[0]), "+f"(d[1]), "+f"(d[2]), "+f"(d[3])
                 : "r"(a[0]), "r"(a[1]), "r"(a[2]), "r"(a[3]), "r"(b0), "r"(b1));
}
#define LDSM4(r, a)                                                               \
    asm volatile("ldmatrix.sync.aligned.m8n8.x4.shared.b16 {%0,%1,%2,%3}, [%4];"  \
        : "=r"((r)[0]), "=r"((r)[1]), "=r"((r)[2]), "=r"((r)[3]) : "r"(a))
__device__ __forceinline__ void cpasync16(uint32_t dst, const void* src) {
    asm volatile("cp.async.cg.shared.global [%0], [%1], 16;" :: "r"(dst), "l"(src) : "memory");
}
#define CP_COMMIT() asm volatile("cp.async.commit_group;" ::: "memory")
#define CP_WAIT(n)  asm volatile("cp.async.wait_group %0;" :: "n"(n) : "memory")
__device__ __forceinline__ void red2(float* addr, float a, float b) {
    asm volatile("red.global.add.v2.f32 [%0], {%1, %2};" :: "l"(addr), "f"(a), "f"(b) : "memory");
}
__device__ __forceinline__ void red1(float* addr, float a) {
    asm volatile("red.global.add.f32 [%0], %1;" :: "l"(addr), "f"(a) : "memory");
}

// ---------------------------------------------------------------------------
// Prep: zero scratch, sniff edge_index dtype, pack weights [chunk][n][k] bf16.
// ---------------------------------------------------------------------------
__global__ void prep_kernel(const unsigned* ei_words,
                            const float* __restrict__ W1,
                            const float* __restrict__ W2,
                            const float* __restrict__ W3) {
    int i = blockIdx.x * 256 + threadIdx.x;
    if (i < NN * DD) g_sums[i] = 0.0f;
    if (i < NN)      g_cnt[i]  = 0.0f;
    if (i == 0) {
        int all0 = 1;
        #pragma unroll
        for (int k = 1; k < 64; k += 2) all0 &= (ei_words[k] == 0u);
        g_idx64 = all0;
    }
    if (i < 5 * 16384) {
        int c = i >> 14, j = i & 16383;
        int n = j >> 7, k = j & 127;
        float v;
        if (c < 3)       v = W1[(c * 128 + k) * DD + n];
        else if (c == 3) v = W2[k * DD + n];
        else             v = W3[k * DD + n];
        g_Wpack[i] = __float2bfloat16_rn(v);
    }
}

// ---------------------------------------------------------------------------
// Edge kernel: 128 edges/CTA, 8 warps (warp w owns m16 tile rows [16w,16w+16)).
// bf16 mma.sync m16n8k16, LDSM frags, cp.async weights, MLP-8 gather, occ 2.
// ---------------------------------------------------------------------------
__global__ void __launch_bounds__(256, 2)
edge_kernel(const float* __restrict__ x, const void* __restrict__ ei,
            const float* __restrict__ ea,
            const float* __restrict__ b1, const float* __restrict__ b2,
            const float* __restrict__ b3)
{
    extern __shared__ uint16_t smem[];
    uint16_t* sA = smem;                          // 128 x 136 halves (272 B rows)
    const uint32_t sAb = smem_u32(sA);
    const uint32_t sW0 = sAb + A_BYTES;           // two weight buffers
    __shared__ int   sDst[TE];
    __shared__ int   sSrc[TE];
    __shared__ float sBias[384];

    const int tid  = threadIdx.x;
    const int wid  = tid >> 5;
    const int lane = tid & 31;
    const int e0   = blockIdx.x * TE;

    if (tid < TE) {
        long long s, d;
        if (g_idx64) {
            const long long* p = (const long long*)ei;
            s = p[e0 + tid]; d = p[NE + e0 + tid];
        } else {
            const int* p = (const int*)ei;
            s = p[e0 + tid]; d = p[NE + e0 + tid];
        }
        sSrc[tid] = (int)s;
        sDst[tid] = (int)d;
        red1(&g_cnt[(int)d], 1.0f);
        sBias[tid] = b1[tid]; sBias[128 + tid] = b2[tid]; sBias[256 + tid] = b3[tid];
    }

    // prefetch weight chunk 0 into buffer 0
    {
        const __nv_bfloat16* src = g_Wpack;
        #pragma unroll
        for (int r = 0; r < 8; r++) {
            int i = tid + r * 256;                // i in [0, 2048)
            int n = i >> 4, q = i & 15;
            cpasync16(sW0 + (uint32_t)(n * 272 + q * 16), src + (size_t)n * 128 + q * 8);
        }
        CP_COMMIT();
    }
    __syncthreads();

    // LDSM lane addressing
    const int sub = lane >> 3, lr = lane & 7;
    const uint32_t aAddr = sAb + (uint32_t)((wid * 16 + (sub & 1) * 8 + lr) * 272 + (sub >> 1) * 16);
    const uint32_t bOff  = (uint32_t)(((sub >> 1) * 8 + lr) * 272 + (sub & 1) * 16);

    float acc[16][4];
    #pragma unroll
    for (int nt = 0; nt < 16; nt++)
        #pragma unroll
        for (int j = 0; j < 4; j++) acc[nt][j] = 0.0f;

    const int ar = wid * 16 + (lane >> 2);   // D-frag base row; second row = +8
    const int kq = lane & 3;

    #pragma unroll 1
    for (int step = 0; step < 5; step++) {
        // ---- gather + fp32->bf16 convert into sA, batched for MLP=8 ----
        // item i = tid + j*256 -> row r = wid + 8j, col-quad = lane
        if (step < 3) {
            #pragma unroll 1
            for (int jb = 0; jb < 2; jb++) {
                float4 v[8];
                #pragma unroll
                for (int u = 0; u < 8; u++) {
                    int r = wid + jb * 64 + u * 8;
                    const float* srow;
                    if (step == 1)      srow = ea + (size_t)(e0 + r) * DD;
                    else if (step == 0) srow = x + (size_t)sDst[r] * DD;
                    else                srow = x + (size_t)sSrc[r] * DD;
                    v[u] = *(const float4*)(srow + lane * 4);
                }
                #pragma unroll
                for (int u = 0; u < 8; u++) {
                    int r = wid + jb * 64 + u * 8;
                    uint2 t;
                    t.x = bf2x(v[u].y, v[u].x);
                    t.y = bf2x(v[u].w, v[u].z);
                    *(uint2*)((char*)sA + r * 272 + lane * 8) = t;
                }
            }
        }

        // ---- prefetch next weight chunk into the other buffer ----
        if (step < 4) {
            const __nv_bfloat16* src = g_Wpack + (size_t)(step + 1) * 16384;
            const uint32_t dstb = sW0 + ((step + 1) & 1) * W_BYTES;
            #pragma unroll
            for (int r = 0; r < 8; r++) {
                int i = tid + r * 256;
                int n = i >> 4, q = i & 15;
                cpasync16(dstb + (uint32_t)(n * 272 + q * 16), src + (size_t)n * 128 + q * 8);
            }
            CP_COMMIT();
            CP_WAIT(1);   // current chunk complete; next may fly
        } else {
            CP_WAIT(0);
        }
        __syncthreads();

        // ---- MMA over full K=128 of this chunk ----
        const uint32_t bBase = sW0 + (step & 1) * W_BYTES + bOff;
        #pragma unroll 1
        for (int ks = 0; ks < 8; ks++) {
            const uint32_t ka = (uint32_t)(ks * 32);   // 16 halves = 32 B
            uint32_t a[4];
            LDSM4(a, aAddr + ka);
            #pragma unroll
            for (int p = 0; p < 8; p++) {
                uint32_t b[4];
                LDSM4(b, bBase + (uint32_t)(p * 16 * 272) + ka);
                mma16(acc[2 * p],     a, b[0], b[1]);
                mma16(acc[2 * p + 1], a, b[2], b[3]);
            }
        }

        // ---- end of layer 1 / layer 2: +bias, ReLU, writeback bf16, zero acc ----
        if (step == 2 || step == 3) {
            const int boff = (step == 2) ? 0 : 128;
            const int cb = 2 * kq;
            #pragma unroll
            for (int nt = 0; nt < 16; nt++) {
                int c = nt * 8 + cb;
                float bv0 = sBias[boff + c], bv1 = sBias[boff + c + 1];
                uint32_t v;
                v = bf2x(fmaxf(acc[nt][1] + bv1, 0.0f), fmaxf(acc[nt][0] + bv0, 0.0f));
                *(uint32_t*)((char*)sA + ar * 272 + 2 * c) = v;
                v = bf2x(fmaxf(acc[nt][3] + bv1, 0.0f), fmaxf(acc[nt][2] + bv0, 0.0f));
                *(uint32_t*)((char*)sA + (ar + 8) * 272 + 2 * c) = v;
                #pragma unroll
                for (int j = 0; j < 4; j++) acc[nt][j] = 0.0f;
            }
        }
        __syncthreads();
    }

    // ---- Epilogue: +b3, scatter-add messages ----
    {
        const int d0 = sDst[ar], d1 = sDst[ar + 8];
        float* p0 = g_sums + (size_t)d0 * DD;
        float* p1 = g_sums + (size_t)d1 * DD;
        const int cb = 2 * kq;
        #pragma unroll
        for (int nt = 0; nt < 16; nt++) {
            int c = nt * 8 + cb;
            float bv0 = sBias[256 + c], bv1 = sBias[256 + c + 1];
            red2(p0 + c, acc[nt][0] + bv0, acc[nt][1] + bv1);
            red2(p1 + c, acc[nt][2] + bv0, acc[nt][3] + bv1);
        }
    }
}

// ---------------------------------------------------------------------------
// Node kernel: 16 nodes/block (512 threads). dh, LN1, FFN, LN2.
// ---------------------------------------------------------------------------
__device__ __forceinline__ float wredsum(float v) {
    #pragma unroll
    for (int o = 16; o > 0; o >>= 1) v += __shfl_xor_sync(0xFFFFFFFFu, v, o);
    return v;
}

__global__ void __launch_bounds__(512)
node_kernel(const float* __restrict__ x,
            const float* __restrict__ F1, const float* __restrict__ bf1,
            const float* __restrict__ F2, const float* __restrict__ bf2,
            const float* __restrict__ g0, const float* __restrict__ be0,
            const float* __restrict__ g1, const float* __restrict__ be1,
            float* __restrict__ out)
{
    const int t = threadIdx.x;
    const int w = t >> 5, lane = t & 31;
    const int n0 = blockIdx.x * 16;

    __shared__ float sH[16][128];
    __shared__ float sF[16][256];

    // Phase A: warp w -> node n0+w: z = x + sums/cnt; LN1 -> sH
    {
        const int n = n0 + w;
        float cnt = fmaxf(g_cnt[n], 1.0f);
        float4 xv = *(const float4*)&x[(size_t)n * DD + lane * 4];
        float4 sv = *(const float4*)&g_sums[(size_t)n * DD + lane * 4];
        float ic = 1.0f / cnt;
        float4 z = make_float4(xv.x + sv.x * ic, xv.y + sv.y * ic,
                               xv.z + sv.z * ic, xv.w + sv.w * ic);
        float s  = wredsum(z.x + z.y + z.z + z.w);
        float q  = wredsum(z.x * z.x + z.y * z.y + z.z * z.z + z.w * z.w);
        float mu = s * (1.0f / DD);
        float var = q * (1.0f / DD) - mu * mu;
        float rs = rsqrtf(var + 1e-6f);
        float4 gv = *(const float4*)&g0[lane * 4];
        float4 bv = *(const float4*)&be0[lane * 4];
        float4 hv;
        hv.x = (z.x - mu) * rs * gv.x + bv.x;
        hv.y = (z.y - mu) * rs * gv.y + bv.y;
        hv.z = (z.z - mu) * rs * gv.z + bv.z;
        hv.w = (z.w - mu) * rs * gv.w + bv.w;
        *(float4*)&sH[w][lane * 4] = hv;
    }
    __syncthreads();

    // Phase B: FFN1. group g=t>>6 (8 groups) handles nodes 2g, 2g+1.
    {
        const int g = t >> 6;
        const int i0 = 2 * g, i1 = 2 * g + 1;
        const int c = (t & 63) * 4;
        float4 a0 = *(const float4*)&bf1[c];
        float4 a1 = a0;
        #pragma unroll 4
        for (int k = 0; k < 128; k++) {
            float4 f = *(const float4*)&F1[(size_t)k * 256 + c];
            float h0 = sH[i0][k], h1 = sH[i1][k];
            a0.x += h0 * f.x; a0.y += h0 * f.y; a0.z += h0 * f.z; a0.w += h0 * f.w;
            a1.x += h1 * f.x; a1.y += h1 * f.y; a1.z += h1 * f.z; a1.w += h1 * f.w;
        }
        a0.x = fmaxf(a0.x, 0.0f); a0.y = fmaxf(a0.y, 0.0f);
        a0.z = fmaxf(a0.z, 0.0f); a0.w = fmaxf(a0.w, 0.0f);
        a1.x = fmaxf(a1.x, 0.0f); a1.y = fmaxf(a1.y, 0.0f);
        a1.z = fmaxf(a1.z, 0.0f); a1.w = fmaxf(a1.w, 0.0f);
        *(float4*)&sF[i0][c] = a0;
        *(float4*)&sF[i1][c] = a1;
    }
    __syncthreads();

    // Phase C: FFN2 + LN2. warp w -> node n0+w, cols lane*4..+3.
    {
        const int n = n0 + w;
        const int c = lane * 4;
        float4 o = *(const float4*)&bf2[c];
        #pragma unroll 4
        for (int k = 0; k < 256; k++) {
            float4 f = *(const float4*)&F2[(size_t)k * DD + c];
            float hk = sF[w][k];
            o.x += hk * f.x; o.y += hk * f.y; o.z += hk * f.z; o.w += hk * f.w;
        }
        float4 hv = *(const float4*)&sH[w][c];
        float4 y = make_float4(hv.x + o.x, hv.y + o.y, hv.z + o.z, hv.w + o.w);
        float s  = wredsum(y.x + y.y + y.z + y.w);
        float q  = wredsum(y.x * y.x + y.y * y.y + y.z * y.z + y.w * y.w);
        float mu = s * (1.0f / DD);
        float var = q * (1.0f / DD) - mu * mu;
        float rs = rsqrtf(var + 1e-6f);
        float4 gv = *(const float4*)&g1[c];
        float4 bv = *(const float4*)&be1[c];
        float4 r;
        r.x = (y.x - mu) * rs * gv.x + bv.x;
        r.y = (y.y - mu) * rs * gv.y + bv.y;
        r.z = (y.z - mu) * rs * gv.z + bv.z;
        r.w = (y.w - mu) * rs * gv.w + bv.w;
        *(float4*)&out[(size_t)n * DD + c] = r;
    }
}

// ---------------------------------------------------------------------------
extern "C" void kernel_launch(void* const* d_in, const int* in_sizes, int n_in,
                              void* d_out, int out_size) {
    const float* x   = (const float*)d_in[0];
    const void*  ei  = d_in[1];
    const float* ea  = (const float*)d_in[2];
    const float* W1  = (const float*)d_in[3];
    const float* b1  = (const float*)d_in[4];
    const float* W2  = (const float*)d_in[5];
    const float* b2  = (const float*)d_in[6];
    const float* W3  = (const float*)d_in[7];
    const float* b3  = (const float*)d_in[8];
    const float* F1  = (const float*)d_in[9];
    const float* bf1 = (const float*)d_in[10];
    const float* F2  = (const float*)d_in[11];
    const float* bf2 = (const float*)d_in[12];
    const float* g0  = (const float*)d_in[13];
    const float* be0 = (const float*)d_in[14];
    const float* g1  = (const float*)d_in[15];
    const float* be1 = (const float*)d_in[16];
    float* out = (float*)d_out;

    static int inited = 0;
    if (!inited) {
        cudaFuncSetAttribute(edge_kernel, cudaFuncAttributeMaxDynamicSharedMemorySize, EDGE_SMEM);
        inited = 1;
    }

    prep_kernel<<<5000, 256>>>((const unsigned*)ei, W1, W2, W3);
    edge_kernel<<<NTILES, 256, EDGE_SMEM>>>(x, ei, ea, b1, b2, b3);
    node_kernel<<<NN / 16, 512>>>(x, F1, bf1, F2, bf2, g0, be0, g1, be1, out);
}

// round 17
// speedup vs baseline: 5.8916x; 1.0050x over previous
#include <cuda_runtime.h>
#include <cuda_bf16.h>
#include <cstdint>

#define NN 10000
#define NE 640000
#define DD 128
#define TE 128                 // edges per CTA
#define NTILES (NE / TE)
#define A_BYTES (TE * 272)               // 34816
#define W_BYTES (128 * 272)              // 34816 per buffer
#define EDGE_SMEM (A_BYTES + 2 * W_BYTES)  // 104448 -> occupancy 2
#define NPB 32                 // nodes per block (node kernel)

__device__ float g_sums[NN * DD];
__device__ float g_cnt[NN];
__device__ int   g_idx64;
__device__ __nv_bfloat16 g_Wpack[5 * 128 * 128];  // [chunk][n][k]: W1(3) | W2 | W3

// ---------------- helpers ----------------
__device__ __forceinline__ uint32_t smem_u32(const void* p) {
    uint32_t a;
    asm("{ .reg .u64 t; cvta.to.shared.u64 t, %1; cvt.u32.u64 %0, t; }" : "=r"(a) : "l"(p));
    return a;
}
__device__ __forceinline__ uint32_t bf2x(float hi, float lo) {
    uint32_t r;
    asm("cvt.rn.bf16x2.f32 %0, %1, %2;" : "=r"(r) : "f"(hi), "f"(lo));
    return r;
}
__device__ __forceinline__ void mma16(float* d, const uint32_t* a, uint32_t b0, uint32_t b1) {
    asm volatile("mma.sync.aligned.m16n8k16.row.col.f32.bf16.bf16.f32 "
                 "{%0,%1,%2,%3}, {%4,%5,%6,%7}, {%8,%9}, {%0,%1,%2,%3};"
                 : "+f"(d[0]), "+f"(d[1]), "+f"(d[2]), "+f"(d[3])
                 : "r"(a[0]), "r"(a[1]), "r"(a[2]), "r"(a[3]), "r"(b0), "r"(b1));
}
#define LDSM4(r, a)                                                               \
    asm volatile("ldmatrix.sync.aligned.m8n8.x4.shared.b16 {%0,%1,%2,%3}, [%4];"  \
        : "=r"((r)[0]), "=r"((r)[1]), "=r"((r)[2]), "=r"((r)[3]) : "r"(a))
__device__ __forceinline__ void cpasync16(uint32_t dst, const void* src) {
    asm volatile("cp.async.cg.shared.global [%0], [%1], 16;" :: "r"(dst), "l"(src) : "memory");
}
#define CP_COMMIT() asm volatile("cp.async.commit_group;" ::: "memory")
#define CP_WAIT(n)  asm volatile("cp.async.wait_group %0;" :: "n"(n) : "memory")
__device__ __forceinline__ void red2(float* addr, float a, float b) {
    asm volatile("red.global.add.v2.f32 [%0], {%1, %2};" :: "l"(addr), "f"(a), "f"(b) : "memory");
}
__device__ __forceinline__ void red1(float* addr, float a) {
    asm volatile("red.global.add.f32 [%0], %1;" :: "l"(addr), "f"(a) : "memory");
}

// ---------------------------------------------------------------------------
// Prep: zero scratch, sniff edge_index dtype, pack weights [chunk][n][k] bf16.
// ---------------------------------------------------------------------------
__global__ void prep_kernel(const unsigned* ei_words,
                            const float* __restrict__ W1,
                            const float* __restrict__ W2,
                            const float* __restrict__ W3) {
    int i = blockIdx.x * 256 + threadIdx.x;
    if (i < NN * DD) g_sums[i] = 0.0f;
    if (i < NN)      g_cnt[i]  = 0.0f;
    if (i == 0) {
        int all0 = 1;
        #pragma unroll
        for (int k = 1; k < 64; k += 2) all0 &= (ei_words[k] == 0u);
        g_idx64 = all0;
    }
    if (i < 5 * 16384) {
        int c = i >> 14, j = i & 16383;
        int n = j >> 7, k = j & 127;
        float v;
        if (c < 3)       v = W1[(c * 128 + k) * DD + n];
        else if (c == 3) v = W2[k * DD + n];
        else             v = W3[k * DD + n];
        g_Wpack[i] = __float2bfloat16_rn(v);
    }
}

// ---------------------------------------------------------------------------
// Edge kernel: 128 edges/CTA, 8 warps (warp w owns m16 tile rows [16w,16w+16)).
// bf16 mma.sync m16n8k16, LDSM frags, cp.async weights, MLP-8 gather, occ 2.
// (unchanged from R16 passing version)
// ---------------------------------------------------------------------------
__global__ void __launch_bounds__(256, 2)
edge_kernel(const float* __restrict__ x, const void* __restrict__ ei,
            const float* __restrict__ ea,
            const float* __restrict__ b1, const float* __restrict__ b2,
            const float* __restrict__ b3)
{
    extern __shared__ uint16_t smem[];
    uint16_t* sA = smem;                          // 128 x 136 halves (272 B rows)
    const uint32_t sAb = smem_u32(sA);
    const uint32_t sW0 = sAb + A_BYTES;           // two weight buffers
    __shared__ int   sDst[TE];
    __shared__ int   sSrc[TE];
    __shared__ float sBias[384];

    const int tid  = threadIdx.x;
    const int wid  = tid >> 5;
    const int lane = tid & 31;
    const int e0   = blockIdx.x * TE;

    if (tid < TE) {
        long long s, d;
        if (g_idx64) {
            const long long* p = (const long long*)ei;
            s = p[e0 + tid]; d = p[NE + e0 + tid];
        } else {
            const int* p = (const int*)ei;
            s = p[e0 + tid]; d = p[NE + e0 + tid];
        }
        sSrc[tid] = (int)s;
        sDst[tid] = (int)d;
        red1(&g_cnt[(int)d], 1.0f);
        sBias[tid] = b1[tid]; sBias[128 + tid] = b2[tid]; sBias[256 + tid] = b3[tid];
    }

    // prefetch weight chunk 0 into buffer 0
    {
        const __nv_bfloat16* src = g_Wpack;
        #pragma unroll
        for (int r = 0; r < 8; r++) {
            int i = tid + r * 256;                // i in [0, 2048)
            int n = i >> 4, q = i & 15;
            cpasync16(sW0 + (uint32_t)(n * 272 + q * 16), src + (size_t)n * 128 + q * 8);
        }
        CP_COMMIT();
    }
    __syncthreads();

    // LDSM lane addressing
    const int sub = lane >> 3, lr = lane & 7;
    const uint32_t aAddr = sAb + (uint32_t)((wid * 16 + (sub & 1) * 8 + lr) * 272 + (sub >> 1) * 16);
    const uint32_t bOff  = (uint32_t)(((sub >> 1) * 8 + lr) * 272 + (sub & 1) * 16);

    float acc[16][4];
    #pragma unroll
    for (int nt = 0; nt < 16; nt++)
        #pragma unroll
        for (int j = 0; j < 4; j++) acc[nt][j] = 0.0f;

    const int ar = wid * 16 + (lane >> 2);   // D-frag base row; second row = +8
    const int kq = lane & 3;

    #pragma unroll 1
    for (int step = 0; step < 5; step++) {
        // ---- gather + fp32->bf16 convert into sA, batched for MLP=8 ----
        if (step < 3) {
            #pragma unroll 1
            for (int jb = 0; jb < 2; jb++) {
                float4 v[8];
                #pragma unroll
                for (int u = 0; u < 8; u++) {
                    int r = wid + jb * 64 + u * 8;
                    const float* srow;
                    if (step == 1)      srow = ea + (size_t)(e0 + r) * DD;
                    else if (step == 0) srow = x + (size_t)sDst[r] * DD;
                    else                srow = x + (size_t)sSrc[r] * DD;
                    v[u] = *(const float4*)(srow + lane * 4);
                }
                #pragma unroll
                for (int u = 0; u < 8; u++) {
                    int r = wid + jb * 64 + u * 8;
                    uint2 t;
                    t.x = bf2x(v[u].y, v[u].x);
                    t.y = bf2x(v[u].w, v[u].z);
                    *(uint2*)((char*)sA + r * 272 + lane * 8) = t;
                }
            }
        }

        // ---- prefetch next weight chunk into the other buffer ----
        if (step < 4) {
            const __nv_bfloat16* src = g_Wpack + (size_t)(step + 1) * 16384;
            const uint32_t dstb = sW0 + ((step + 1) & 1) * W_BYTES;
            #pragma unroll
            for (int r = 0; r < 8; r++) {
                int i = tid + r * 256;
                int n = i >> 4, q = i & 15;
                cpasync16(dstb + (uint32_t)(n * 272 + q * 16), src + (size_t)n * 128 + q * 8);
            }
            CP_COMMIT();
            CP_WAIT(1);
        } else {
            CP_WAIT(0);
        }
        __syncthreads();

        // ---- MMA over full K=128 of this chunk ----
        const uint32_t bBase = sW0 + (step & 1) * W_BYTES + bOff;
        #pragma unroll 1
        for (int ks = 0; ks < 8; ks++) {
            const uint32_t ka = (uint32_t)(ks * 32);
            uint32_t a[4];
            LDSM4(a, aAddr + ka);
            #pragma unroll
            for (int p = 0; p < 8; p++) {
                uint32_t b[4];
                LDSM4(b, bBase + (uint32_t)(p * 16 * 272) + ka);
                mma16(acc[2 * p],     a, b[0], b[1]);
                mma16(acc[2 * p + 1], a, b[2], b[3]);
            }
        }

        // ---- end of layer 1 / layer 2: +bias, ReLU, writeback bf16, zero acc ----
        if (step == 2 || step == 3) {
            const int boff = (step == 2) ? 0 : 128;
            const int cb = 2 * kq;
            #pragma unroll
            for (int nt = 0; nt < 16; nt++) {
                int c = nt * 8 + cb;
                float bv0 = sBias[boff + c], bv1 = sBias[boff + c + 1];
                uint32_t v;
                v = bf2x(fmaxf(acc[nt][1] + bv1, 0.0f), fmaxf(acc[nt][0] + bv0, 0.0f));
                *(uint32_t*)((char*)sA + ar * 272 + 2 * c) = v;
                v = bf2x(fmaxf(acc[nt][3] + bv1, 0.0f), fmaxf(acc[nt][2] + bv0, 0.0f));
                *(uint32_t*)((char*)sA + (ar + 8) * 272 + 2 * c) = v;
                #pragma unroll
                for (int j = 0; j < 4; j++) acc[nt][j] = 0.0f;
            }
        }
        __syncthreads();
    }

    // ---- Epilogue: +b3, scatter-add messages ----
    {
        const int d0 = sDst[ar], d1 = sDst[ar + 8];
        float* p0 = g_sums + (size_t)d0 * DD;
        float* p1 = g_sums + (size_t)d1 * DD;
        const int cb = 2 * kq;
        #pragma unroll
        for (int nt = 0; nt < 16; nt++) {
            int c = nt * 8 + cb;
            float bv0 = sBias[256 + c], bv1 = sBias[256 + c + 1];
            red2(p0 + c, acc[nt][0] + bv0, acc[nt][1] + bv1);
            red2(p1 + c, acc[nt][2] + bv0, acc[nt][3] + bv1);
        }
    }
}

// ---------------------------------------------------------------------------
// Node kernel v3: 32 nodes/block (256 threads), register-blocked FFN.
// Phase B: 4 groups x 64 thr, 8 nodes per group  -> F1 read 4x/block.
// Phase C: 8 warps, 4 nodes per warp             -> F2 read 8x/block.
// ---------------------------------------------------------------------------
__device__ __forceinline__ float wredsum(float v) {
    #pragma unroll
    for (int o = 16; o > 0; o >>= 1) v += __shfl_xor_sync(0xFFFFFFFFu, v, o);
    return v;
}

__global__ void __launch_bounds__(256)
node_kernel(const float* __restrict__ x,
            const float* __restrict__ F1, const float* __restrict__ bf1,
            const float* __restrict__ F2, const float* __restrict__ bf2,
            const float* __restrict__ g0, const float* __restrict__ be0,
            const float* __restrict__ g1, const float* __restrict__ be1,
            float* __restrict__ out)
{
    const int t = threadIdx.x;
    const int w = t >> 5, lane = t & 31;
    const int n0 = blockIdx.x * NPB;

    __shared__ float sH[NPB][128];
    __shared__ float sF[NPB][256];

    // Phase A: 8 warps x 4 reps; warp handles node n0 + w + rep*8 -> LN1 -> sH
    #pragma unroll
    for (int rep = 0; rep < 4; rep++) {
        const int ni = w + rep * 8;
        const int n = min(n0 + ni, NN - 1);
        float cnt = fmaxf(g_cnt[n], 1.0f);
        float4 xv = *(const float4*)&x[(size_t)n * DD + lane * 4];
        float4 sv = *(const float4*)&g_sums[(size_t)n * DD + lane * 4];
        float ic = 1.0f / cnt;
        float4 z = make_float4(xv.x + sv.x * ic, xv.y + sv.y * ic,
                               xv.z + sv.z * ic, xv.w + sv.w * ic);
        float s  = wredsum(z.x + z.y + z.z + z.w);
        float q  = wredsum(z.x * z.x + z.y * z.y + z.z * z.z + z.w * z.w);
        float mu = s * (1.0f / DD);
        float var = q * (1.0f / DD) - mu * mu;
        float rs = rsqrtf(var + 1e-6f);
        float4 gv = *(const float4*)&g0[lane * 4];
        float4 bv = *(const float4*)&be0[lane * 4];
        float4 hv;
        hv.x = (z.x - mu) * rs * gv.x + bv.x;
        hv.y = (z.y - mu) * rs * gv.y + bv.y;
        hv.z = (z.z - mu) * rs * gv.z + bv.z;
        hv.w = (z.w - mu) * rs * gv.w + bv.w;
        *(float4*)&sH[ni][lane * 4] = hv;
    }
    __syncthreads();

    // Phase B: FFN1. group g = t>>6 (4 groups), cols c=(t&63)*4, 8 nodes/group.
    {
        const int g = t >> 6;
        const int c = (t & 63) * 4;
        const float4 binit = *(const float4*)&bf1[c];
        float4 a[8];
        #pragma unroll
        for (int i = 0; i < 8; i++) a[i] = binit;
        #pragma unroll 2
        for (int k = 0; k < 128; k++) {
            float4 f = *(const float4*)&F1[(size_t)k * 256 + c];
            #pragma unroll
            for (int i = 0; i < 8; i++) {
                float h = sH[g * 8 + i][k];
                a[i].x += h * f.x; a[i].y += h * f.y;
                a[i].z += h * f.z; a[i].w += h * f.w;
            }
        }
        #pragma unroll
        for (int i = 0; i < 8; i++) {
            a[i].x = fmaxf(a[i].x, 0.0f); a[i].y = fmaxf(a[i].y, 0.0f);
            a[i].z = fmaxf(a[i].z, 0.0f); a[i].w = fmaxf(a[i].w, 0.0f);
            *(float4*)&sF[g * 8 + i][c] = a[i];
        }
    }
    __syncthreads();

    // Phase C: FFN2 + LN2. 8 warps, 4 nodes/warp, cols lane*4..+3.
    {
        const int c = lane * 4;
        const float4 binit = *(const float4*)&bf2[c];
        float4 o[4];
        #pragma unroll
        for (int i = 0; i < 4; i++) o[i] = binit;
        #pragma unroll 2
        for (int k = 0; k < 256; k++) {
            float4 f = *(const float4*)&F2[(size_t)k * DD + c];
            #pragma unroll
            for (int i = 0; i < 4; i++) {
                float hk = sF[w * 4 + i][k];
                o[i].x += hk * f.x; o[i].y += hk * f.y;
                o[i].z += hk * f.z; o[i].w += hk * f.w;
            }
        }
        const float4 gv = *(const float4*)&g1[c];
        const float4 bv = *(const float4*)&be1[c];
        #pragma unroll
        for (int i = 0; i < 4; i++) {
            const int ni = w * 4 + i;
            const int n = n0 + ni;
            float4 hv = *(const float4*)&sH[ni][c];
            float4 y = make_float4(hv.x + o[i].x, hv.y + o[i].y,
                                   hv.z + o[i].z, hv.w + o[i].w);
            float s  = wredsum(y.x + y.y + y.z + y.w);
            float q  = wredsum(y.x * y.x + y.y * y.y + y.z * y.z + y.w * y.w);
            float mu = s * (1.0f / DD);
            float var = q * (1.0f / DD) - mu * mu;
            float rs = rsqrtf(var + 1e-6f);
            float4 r;
            r.x = (y.x - mu) * rs * gv.x + bv.x;
            r.y = (y.y - mu) * rs * gv.y + bv.y;
            r.z = (y.z - mu) * rs * gv.z + bv.z;
            r.w = (y.w - mu) * rs * gv.w + bv.w;
            if (n < NN) *(float4*)&out[(size_t)n * DD + c] = r;
        }
    }
}

// ---------------------------------------------------------------------------
extern "C" void kernel_launch(void* const* d_in, const int* in_sizes, int n_in,
                              void* d_out, int out_size) {
    const float* x   = (const float*)d_in[0];
    const void*  ei  = d_in[1];
    const float* ea  = (const float*)d_in[2];
    const float* W1  = (const float*)d_in[3];
    const float* b1  = (const float*)d_in[4];
    const float* W2  = (const float*)d_in[5];
    const float* b2  = (const float*)d_in[6];
    const float* W3  = (const float*)d_in[7];
    const float* b3  = (const float*)d_in[8];
    const float* F1  = (const float*)d_in[9];
    const float* bf1 = (const float*)d_in[10];
    const float* F2  = (const float*)d_in[11];
    const float* bf2 = (const float*)d_in[12];
    const float* g0  = (const float*)d_in[13];
    const float* be0 = (const float*)d_in[14];
    const float* g1  = (const float*)d_in[15];
    const float* be1 = (const float*)d_in[16];
    float* out = (float*)d_out;

    static int inited = 0;
    if (!inited) {
        cudaFuncSetAttribute(edge_kernel, cudaFuncAttributeMaxDynamicSharedMemorySize, EDGE_SMEM);
        inited = 1;
    }

    prep_kernel<<<5000, 256>>>((const unsigned*)ei, W1, W2, W3);
    edge_kernel<<<NTILES, 256, EDGE_SMEM>>>(x, ei, ea, b1, b2, b3);
    node_kernel<<<(NN + NPB - 1) / NPB, 256>>>(x, F1, bf1, F2, bf2, g0, be0, g1, be1, out);
}